// round 1
// baseline (speedup 1.0000x reference)
#include <cuda_runtime.h>
#include <math.h>

#define NB 8
#define SEQ 512
#define MAXSEQ 4096
#define DIM 512
#define INTER 1024
#define NLAYERS 4
#define P1 516              // 512 real + 3 conv-boundary + 1 "constant" representative
#define CONST_W 3581.0f     // positions 515..4095 collapse to one representative

// ---- scratch (static device globals; no allocation) ----
__device__ float g_x [NB*SEQ*DIM];     // activations (residual stream), p<512
__device__ float g_xn[NB*P1 *DIM];     // post dwconv+LN
__device__ float g_h [NB*P1 *INTER];   // post pw1+GELU
__device__ float g_alpha[NB*INTER];    // GRN multiplicative factor per (b, i)

// ================= embed + abs pos enc =================
__global__ void embed_kernel(const int* __restrict__ text, const float* __restrict__ emb) {
    int bp = blockIdx.x;               // b*512 + p
    int p  = bp & 511;
    int b  = bp >> 9;
    int tok = text[b*SEQ + p] + 1;     // 1..256, never 0
    const float* erow = emb + tok*DIM;
    float* orow = g_x + bp*DIM;
    for (int c = threadIdx.x; c < DIM; c += blockDim.x) {
        int i = (c < 256) ? c : (c - 256);
        double f   = exp(-9.210340371976184 * (double)i / 256.0);   // 10000^(-i/256)
        double ang = (double)p * f;
        float pe = (c < 256) ? (float)cos(ang) : (float)sin(ang);
        orow[c] = erow[c] + pe;
    }
}

// ================= dwconv(k=7) + LayerNorm =================
__global__ void convln_kernel(const float* __restrict__ dw_w, const float* __restrict__ dw_b,
                              const float* __restrict__ ln_g, const float* __restrict__ ln_b) {
    int bp = blockIdx.x;               // b*P1 + p
    int b = bp / P1;
    int p = bp - b*P1;
    int t = threadIdx.x;               // 128 threads, 4 channels each (c = t + j*128)
    float y[4];
    #pragma unroll
    for (int j = 0; j < 4; j++) {
        int c = t + j*128;
        float acc = dw_b[c];
        #pragma unroll
        for (int k = 0; k < 7; k++) {
            int pp = p - 3 + k;
            if (pp >= 0 && pp < SEQ)
                acc += dw_w[k*DIM + c] * g_x[(b*SEQ + pp)*DIM + c];
        }
        y[j] = acc;
    }
    float s  = y[0]+y[1]+y[2]+y[3];
    float s2 = y[0]*y[0]+y[1]*y[1]+y[2]*y[2]+y[3]*y[3];
    #pragma unroll
    for (int off = 16; off; off >>= 1) {
        s  += __shfl_xor_sync(0xffffffffu, s,  off);
        s2 += __shfl_xor_sync(0xffffffffu, s2, off);
    }
    __shared__ float sh[8];
    int w = t >> 5;
    if ((t & 31) == 0) { sh[w] = s; sh[4+w] = s2; }
    __syncthreads();
    float S  = sh[0]+sh[1]+sh[2]+sh[3];
    float S2 = sh[4]+sh[5]+sh[6]+sh[7];
    float mean = S * (1.0f/512.0f);
    float var  = S2 * (1.0f/512.0f) - mean*mean;
    float inv  = rsqrtf(var + 1e-6f);
    float* orow = g_xn + (size_t)bp * DIM;
    #pragma unroll
    for (int j = 0; j < 4; j++) {
        int c = t + j*128;
        orow[c] = (y[j] - mean) * inv * ln_g[c] + ln_b[c];
    }
}

// ================= GEMM1: h = gelu(xn @ pw1_w + pw1_b) =================
// M = NB*P1 = 4128, K = 512, N = 1024
#define BM 64
#define BN 64
#define BK 16
__global__ void gemm1_kernel(const float* __restrict__ W, const float* __restrict__ bias) {
    __shared__ float As[BK][BM+4];
    __shared__ float Bs[BK][BN];
    const int M = NB*P1, K = DIM, N = INTER;
    int m0 = blockIdx.y * BM, n0 = blockIdx.x * BN;
    int t = threadIdx.x;
    int tx = t & 15, ty = t >> 4;
    int aRow = t >> 2,  aCol = (t & 3)  * 4;
    int bRow = t >> 4,  bCol = (t & 15) * 4;
    float acc[4][4] = {};
    for (int k0 = 0; k0 < K; k0 += BK) {
        float4 a4 = make_float4(0.f,0.f,0.f,0.f);
        int m = m0 + aRow;
        if (m < M) a4 = *(const float4*)&g_xn[(size_t)m*K + k0 + aCol];
        As[aCol+0][aRow] = a4.x; As[aCol+1][aRow] = a4.y;
        As[aCol+2][aRow] = a4.z; As[aCol+3][aRow] = a4.w;
        *(float4*)&Bs[bRow][bCol] = *(const float4*)&W[(size_t)(k0+bRow)*N + n0 + bCol];
        __syncthreads();
        #pragma unroll
        for (int kk = 0; kk < BK; kk++) {
            float4 av = *(float4*)&As[kk][ty*4];
            float4 bv = *(float4*)&Bs[kk][tx*4];
            float a[4] = {av.x, av.y, av.z, av.w};
            float bb[4] = {bv.x, bv.y, bv.z, bv.w};
            #pragma unroll
            for (int i = 0; i < 4; i++)
                #pragma unroll
                for (int j = 0; j < 4; j++)
                    acc[i][j] += a[i] * bb[j];
        }
        __syncthreads();
    }
    #pragma unroll
    for (int i = 0; i < 4; i++) {
        int m = m0 + ty*4 + i;
        if (m >= M) continue;
        #pragma unroll
        for (int j = 0; j < 4; j++) {
            int n = n0 + tx*4 + j;
            float v = acc[i][j] + bias[n];
            g_h[(size_t)m*N + n] = 0.5f * v * (1.0f + erff(v * 0.7071067811865476f));
        }
    }
}

// ================= GRN statistics: alpha = grn_g * nx + 1 =================
__global__ void grn_kernel(const float* __restrict__ grn_g) {
    int b = blockIdx.x;
    int i = threadIdx.x;               // 1024 threads
    const float* hb = g_h + (size_t)b*P1*INTER + i;
    float s = 0.f;
    #pragma unroll 5
    for (int p = 0; p < 515; p++) { float v = hb[(size_t)p*INTER]; s += v*v; }
    { float v = hb[(size_t)515*INTER]; s += CONST_W * v * v; }   // p=515..4095 identical
    float gx = sqrtf(s);
    // block mean of gx over 1024 channels
    float r = gx;
    #pragma unroll
    for (int off = 16; off; off >>= 1) r += __shfl_xor_sync(0xffffffffu, r, off);
    __shared__ float sh[32];
    __shared__ float meansh;
    if ((i & 31) == 0) sh[i >> 5] = r;
    __syncthreads();
    if (i < 32) {
        float v = sh[i];
        #pragma unroll
        for (int off = 16; off; off >>= 1) v += __shfl_xor_sync(0xffffffffu, v, off);
        if (i == 0) meansh = v * (1.0f/1024.0f);
    }
    __syncthreads();
    float nx = gx / (meansh + 1e-6f);
    g_alpha[b*INTER + i] = grn_g[i] * nx + 1.0f;
}

// ================= GEMM2: x = x + (h*alpha + grn_b) @ pw2_w + pw2_b =================
// M = NB*SEQ = 4096, K = 1024, N = 512
__global__ void gemm2_kernel(const float* __restrict__ W, const float* __restrict__ bias,
                             const float* __restrict__ grn_b) {
    __shared__ float As[BK][BM+4];
    __shared__ float Bs[BK][BN];
    const int K = INTER, N = DIM;
    int m0 = blockIdx.y * BM, n0 = blockIdx.x * BN;
    int t = threadIdx.x;
    int tx = t & 15, ty = t >> 4;
    int aRow = t >> 2,  aCol = (t & 3)  * 4;
    int bRow = t >> 4,  bCol = (t & 15) * 4;
    int bb_ = (m0 >> 9);                         // batch constant per 64-row tile
    float acc[4][4] = {};
    for (int k0 = 0; k0 < K; k0 += BK) {
        int m = m0 + aRow;                       // < 4096 always
        int p = m & 511;
        const float* hrow = g_h + ((size_t)(bb_*P1 + p))*INTER;
        float4 h4  = *(const float4*)&hrow[k0 + aCol];
        float4 al4 = *(const float4*)&g_alpha[bb_*INTER + k0 + aCol];
        float4 gb4 = *(const float4*)&grn_b[k0 + aCol];
        As[aCol+0][aRow] = h4.x*al4.x + gb4.x;
        As[aCol+1][aRow] = h4.y*al4.y + gb4.y;
        As[aCol+2][aRow] = h4.z*al4.z + gb4.z;
        As[aCol+3][aRow] = h4.w*al4.w + gb4.w;
        *(float4*)&Bs[bRow][bCol] = *(const float4*)&W[(size_t)(k0+bRow)*N + n0 + bCol];
        __syncthreads();
        #pragma unroll
        for (int kk = 0; kk < BK; kk++) {
            float4 av = *(float4*)&As[kk][ty*4];
            float4 bv = *(float4*)&Bs[kk][tx*4];
            float a[4] = {av.x, av.y, av.z, av.w};
            float bbv[4] = {bv.x, bv.y, bv.z, bv.w};
            #pragma unroll
            for (int i = 0; i < 4; i++)
                #pragma unroll
                for (int j = 0; j < 4; j++)
                    acc[i][j] += a[i] * bbv[j];
        }
        __syncthreads();
    }
    #pragma unroll
    for (int i = 0; i < 4; i++) {
        int m = m0 + ty*4 + i;
        #pragma unroll
        for (int j = 0; j < 4; j++) {
            int n = n0 + tx*4 + j;
            size_t xi = (size_t)m*DIM + n;
            g_x[xi] = g_x[xi] + acc[i][j] + bias[n];   // residual fused
        }
    }
}

// ================= length-regulator upsample =================
__global__ void upsample_kernel(const int* __restrict__ seq_len, float* __restrict__ out) {
    int bp = blockIdx.x;               // b*4096 + p
    int b = bp >> 12, p = bp & 4095;
    int al = seq_len[b];
    float4* orow = (float4*)(out + (size_t)bp * DIM);
    if (p >= al) {
        for (int c = threadIdx.x; c < DIM/4; c += blockDim.x)
            orow[c] = make_float4(0.f,0.f,0.f,0.f);
        return;
    }
    int base  = al >> 9;               // al / 512  (tl = 512 structurally)
    int rem   = al & 511;
    int split = (512 - rem) * base;
    int j = (p < split) ? (p / base) : ((512 - rem) + (p - split) / (base + 1));
    if (j > 511) j = 511;
    const float4* xrow = (const float4*)(g_x + (size_t)(b*SEQ + j)*DIM);
    for (int c = threadIdx.x; c < DIM/4; c += blockDim.x) orow[c] = xrow[c];
}

extern "C" void kernel_launch(void* const* d_in, const int* in_sizes, int n_in,
                              void* d_out, int out_size) {
    const int*   text    = (const int*)  d_in[0];
    const int*   seq_len = (const int*)  d_in[1];
    const float* emb     = (const float*)d_in[2];
    const float* dw_w    = (const float*)d_in[3];
    const float* dw_b    = (const float*)d_in[4];
    const float* ln_g    = (const float*)d_in[5];
    const float* ln_b    = (const float*)d_in[6];
    const float* pw1_w   = (const float*)d_in[7];
    const float* pw1_b   = (const float*)d_in[8];
    const float* grn_g   = (const float*)d_in[9];
    const float* grn_b   = (const float*)d_in[10];
    const float* pw2_w   = (const float*)d_in[11];
    const float* pw2_b   = (const float*)d_in[12];
    float* out = (float*)d_out;

    embed_kernel<<<NB*SEQ, 128>>>(text, emb);
    for (int l = 0; l < NLAYERS; l++) {
        convln_kernel<<<NB*P1, 128>>>(dw_w + l*7*DIM, dw_b + l*DIM,
                                      ln_g + l*DIM, ln_b + l*DIM);
        dim3 g1(INTER/BN, (NB*P1 + BM - 1)/BM);
        gemm1_kernel<<<g1, 256>>>(pw1_w + (size_t)l*DIM*INTER, pw1_b + l*INTER);
        grn_kernel<<<NB, 1024>>>(grn_g + l*INTER);
        dim3 g2(DIM/BN, (NB*SEQ)/BM);
        gemm2_kernel<<<g2, 256>>>(pw2_w + (size_t)l*INTER*DIM, pw2_b + l*DIM,
                                  grn_b + l*INTER);
    }
    upsample_kernel<<<NB*MAXSEQ, 128>>>(seq_len, out);
}

// round 3
// speedup vs baseline: 1.8731x; 1.8731x over previous
#include <cuda_runtime.h>
#include <cuda_bf16.h>
#include <math.h>
#include <stdint.h>

#define NB 8
#define SEQ 512
#define MAXSEQ 4096
#define DIM 512
#define INTER 1024
#define NLAYERS 4
#define P1 516
#define MPAD 640              // padded rows/batch for GEMM1 (multiple of 128)
#define CONST_W 3581.0f       // positions 515..4095 identical

// ---------------- scratch (__device__ globals; zero-initialized) ----------------
__device__ float         g_x   [NB*SEQ*DIM];     // residual stream fp32
__device__ __nv_bfloat16 g_a1h [NB*MPAD*DIM];    // GEMM1 A hi (rows >=516 stay 0)
__device__ __nv_bfloat16 g_a1l [NB*MPAD*DIM];    // GEMM1 A lo
__device__ float         g_h   [NB*SEQ*INTER];   // gelu output (p<512 only)
__device__ __nv_bfloat16 g_a2h [NB*SEQ*INTER];   // GEMM2 A hi
__device__ __nv_bfloat16 g_a2l [NB*SEQ*INTER];
__device__ __nv_bfloat16 g_w1h [NLAYERS*INTER*DIM];  // pw1_w transposed [N][K] hi
__device__ __nv_bfloat16 g_w1l [NLAYERS*INTER*DIM];
__device__ __nv_bfloat16 g_w2h [NLAYERS*DIM*INTER];  // pw2_w transposed [N][K] hi
__device__ __nv_bfloat16 g_w2l [NLAYERS*DIM*INTER];
__device__ float         g_sumsq[NB*INTER];      // GRN sums (reset by alpha_kernel)
__device__ float         g_alpha[NB*INTER];

// ---------------- helpers ----------------
__device__ __forceinline__ uint32_t smem_u32(const void* p) {
    uint32_t a;
    asm("{ .reg .u64 t; cvta.to.shared.u64 t, %1; cvt.u32.u64 %0, t; }" : "=r"(a) : "l"(p));
    return a;
}
__device__ __forceinline__ uint32_t swz(uint32_t off) {
    return off ^ ((off >> 3) & 0x70u);
}

// ---------------- stage loader: 128x64 bf16 tiles for A and B via cp.async ----------------
__device__ __forceinline__ void stage_load(const __nv_bfloat16* Ag, const __nv_bfloat16* Bg,
                                           int K, uint32_t sA, uint32_t sB, int t) {
    #pragma unroll
    for (int i = 0; i < 4; i++) {
        int idx = t + i * 256;
        int row = idx >> 3, kg = idx & 7;
        uint32_t o = swz((uint32_t)row * 128u + (uint32_t)kg * 16u);
        const char* srcA = (const char*)(Ag + (size_t)row * K) + kg * 16;
        asm volatile("cp.async.cg.shared.global [%0], [%1], 16;" :: "r"(sA + o), "l"(srcA));
        const char* srcB = (const char*)(Bg + (size_t)row * K) + kg * 16;
        asm volatile("cp.async.cg.shared.global [%0], [%1], 16;" :: "r"(sB + o), "l"(srcB));
    }
}

// ---------------- compute one 64-K stage ----------------
__device__ __forceinline__ void compute_stage(uint32_t sA, uint32_t sB,
                                              int warpM, int warpN, int lane,
                                              float acc[4][4][4]) {
    #pragma unroll
    for (int ks = 0; ks < 4; ks++) {
        uint32_t kb = (uint32_t)ks * 32u + (uint32_t)(lane >> 4) * 16u;
        uint32_t a_frag[4][4];
        #pragma unroll
        for (int i = 0; i < 4; i++) {
            uint32_t off = (uint32_t)(warpM * 64 + i * 16 + (lane & 15)) * 128u + kb;
            uint32_t addr = sA + swz(off);
            asm volatile("ldmatrix.sync.aligned.m8n8.x4.shared.b16 {%0,%1,%2,%3}, [%4];"
                : "=r"(a_frag[i][0]), "=r"(a_frag[i][1]), "=r"(a_frag[i][2]), "=r"(a_frag[i][3])
                : "r"(addr));
        }
        uint32_t b_frag[4][2];
        #pragma unroll
        for (int jj = 0; jj < 2; jj++) {
            uint32_t off = (uint32_t)(warpN * 32 + jj * 16 + (lane & 15)) * 128u + kb;
            uint32_t addr = sB + swz(off);
            uint32_t r0, r1, r2, r3;
            asm volatile("ldmatrix.sync.aligned.m8n8.x4.shared.b16 {%0,%1,%2,%3}, [%4];"
                : "=r"(r0), "=r"(r1), "=r"(r2), "=r"(r3) : "r"(addr));
            b_frag[jj*2+0][0] = r0; b_frag[jj*2+0][1] = r2;
            b_frag[jj*2+1][0] = r1; b_frag[jj*2+1][1] = r3;
        }
        #pragma unroll
        for (int i = 0; i < 4; i++)
            #pragma unroll
            for (int j = 0; j < 4; j++)
                asm volatile(
                    "mma.sync.aligned.m16n8k16.row.col.f32.bf16.bf16.f32 "
                    "{%0,%1,%2,%3}, {%4,%5,%6,%7}, {%8,%9}, {%0,%1,%2,%3};"
                    : "+f"(acc[i][j][0]), "+f"(acc[i][j][1]),
                      "+f"(acc[i][j][2]), "+f"(acc[i][j][3])
                    : "r"(a_frag[i][0]), "r"(a_frag[i][1]),
                      "r"(a_frag[i][2]), "r"(a_frag[i][3]),
                      "r"(b_frag[j][0]), "r"(b_frag[j][1]));
    }
}

// ---------------- shared mainloop: acc = A x B^T with hi/lo split (3 phases) ----------------
__device__ __forceinline__ void mma_mainloop(
    const __nv_bfloat16* a_hi, const __nv_bfloat16* a_lo,
    const __nv_bfloat16* b_hi, const __nv_bfloat16* b_lo,
    int K, int pc /* chunks per phase */, int m0, int n0,
    uint32_t smem_base, int t, int warpM, int warpN, int lane,
    float acc[4][4][4]) {
    int nchunks = 3 * pc;
    // prefetch chunk 0 (phase 0: hi x hi)
    stage_load(a_hi + (size_t)m0 * K, b_hi + (size_t)n0 * K, K,
               smem_base, smem_base + 16384u, t);
    asm volatile("cp.async.commit_group;" ::: "memory");
    for (int kc = 0; kc < nchunks; kc++) {
        if (kc + 1 < nchunks) {
            int nk = kc + 1;
            int ph = nk / pc;
            int k0 = (nk - ph * pc) * 64;
            const __nv_bfloat16* As = (ph == 1) ? a_lo : a_hi;
            const __nv_bfloat16* Bs = (ph == 2) ? b_lo : b_hi;
            uint32_t sb = smem_base + (uint32_t)(nk & 1) * 32768u;
            stage_load(As + (size_t)m0 * K + k0, Bs + (size_t)n0 * K + k0, K,
                       sb, sb + 16384u, t);
        }
        asm volatile("cp.async.commit_group;" ::: "memory");
        asm volatile("cp.async.wait_group 1;" ::: "memory");
        __syncthreads();
        uint32_t sb = smem_base + (uint32_t)(kc & 1) * 32768u;
        compute_stage(sb, sb + 16384u, warpM, warpN, lane, acc);
        __syncthreads();
    }
}

__device__ __forceinline__ float gelu_exact(float v) {
    return 0.5f * v * (1.0f + erff(v * 0.7071067811865476f));
}

// ---------------- GEMM1: h = gelu(A1 @ W1t^T + b), fused GRN sumsq ----------------
__global__ void __launch_bounds__(256) gemm1_mma(int l, const float* __restrict__ bias) {
    extern __shared__ char smem[];
    uint32_t sbase = smem_u32(smem);
    int t = threadIdx.x, lane = t & 31, wid = t >> 5;
    int warpM = wid & 1, warpN = wid >> 1;
    int n0 = blockIdx.x * 128, m0 = blockIdx.y * 128;
    float acc[4][4][4] = {};
    mma_mainloop(g_a1h, g_a1l,
                 g_w1h + (size_t)l * INTER * DIM, g_w1l + (size_t)l * INTER * DIM,
                 DIM, 8, m0, n0, sbase, t, warpM, warpN, lane, acc);
    int b  = m0 / MPAD;
    int p0 = m0 - b * MPAD;
    float colsum[4][2] = {};
    #pragma unroll
    for (int i = 0; i < 4; i++) {
        int rowbase = p0 + warpM * 64 + i * 16 + (lane >> 2);
        #pragma unroll
        for (int half = 0; half < 2; half++) {
            int p = rowbase + 8 * half;
            float wgt = (p < 515) ? 1.0f : ((p == 515) ? CONST_W : 0.0f);
            #pragma unroll
            for (int j = 0; j < 4; j++) {
                int n = n0 + warpN * 32 + j * 8 + (lane & 3) * 2;
                float g0 = gelu_exact(acc[i][j][half*2+0] + bias[n]);
                float g1 = gelu_exact(acc[i][j][half*2+1] + bias[n+1]);
                colsum[j][0] += wgt * g0 * g0;
                colsum[j][1] += wgt * g1 * g1;
                if (p < 512) {
                    float2 v2 = make_float2(g0, g1);
                    *(float2*)&g_h[((size_t)(b * SEQ + p)) * INTER + n] = v2;
                }
            }
        }
    }
    // reduce column sums over the 8 lanes covering the same n columns
    #pragma unroll
    for (int j = 0; j < 4; j++)
        #pragma unroll
        for (int s = 0; s < 2; s++) {
            float v = colsum[j][s];
            v += __shfl_xor_sync(0xffffffffu, v, 4);
            v += __shfl_xor_sync(0xffffffffu, v, 8);
            v += __shfl_xor_sync(0xffffffffu, v, 16);
            colsum[j][s] = v;
        }
    if (lane < 4) {
        #pragma unroll
        for (int j = 0; j < 4; j++) {
            int n = n0 + warpN * 32 + j * 8 + lane * 2;
            atomicAdd(&g_sumsq[b * INTER + n],     colsum[j][0]);
            atomicAdd(&g_sumsq[b * INTER + n + 1], colsum[j][1]);
        }
    }
}

// ---------------- GEMM2: x += A2 @ W2t^T + b ----------------
__global__ void __launch_bounds__(256) gemm2_mma(int l, const float* __restrict__ bias) {
    extern __shared__ char smem[];
    uint32_t sbase = smem_u32(smem);
    int t = threadIdx.x, lane = t & 31, wid = t >> 5;
    int warpM = wid & 1, warpN = wid >> 1;
    int n0 = blockIdx.x * 128, m0 = blockIdx.y * 128;
    float acc[4][4][4] = {};
    mma_mainloop(g_a2h, g_a2l,
                 g_w2h + (size_t)l * DIM * INTER, g_w2l + (size_t)l * DIM * INTER,
                 INTER, 16, m0, n0, sbase, t, warpM, warpN, lane, acc);
    #pragma unroll
    for (int i = 0; i < 4; i++) {
        int rowbase = m0 + warpM * 64 + i * 16 + (lane >> 2);
        #pragma unroll
        for (int half = 0; half < 2; half++) {
            int m = rowbase + 8 * half;
            #pragma unroll
            for (int j = 0; j < 4; j++) {
                int n = n0 + warpN * 32 + j * 8 + (lane & 3) * 2;
                size_t xo = (size_t)m * DIM + n;
                float2 xv = *(float2*)&g_x[xo];
                xv.x += acc[i][j][half*2+0] + bias[n];
                xv.y += acc[i][j][half*2+1] + bias[n+1];
                *(float2*)&g_x[xo] = xv;
            }
        }
    }
}

// ---------------- embed + abs pos enc ----------------
__global__ void embed_kernel(const int* __restrict__ text, const float* __restrict__ emb) {
    int bp = blockIdx.x;
    int p = bp & 511, b = bp >> 9;
    int tok = text[b * SEQ + p] + 1;
    const float* erow = emb + (size_t)tok * DIM;
    float* orow = g_x + (size_t)bp * DIM;
    for (int c = threadIdx.x; c < DIM; c += blockDim.x) {
        int i = (c < 256) ? c : (c - 256);
        double f   = exp(-9.210340371976184 * (double)i / 256.0);
        double ang = (double)p * f;
        float pe = (c < 256) ? (float)cos(ang) : (float)sin(ang);
        orow[c] = erow[c] + pe;
    }
}

// ---------------- dwconv(k=7) + LayerNorm -> bf16 hi/lo ----------------
__global__ void convln_kernel(const float* __restrict__ dw_w, const float* __restrict__ dw_b,
                              const float* __restrict__ ln_g, const float* __restrict__ ln_b) {
    int bp = blockIdx.x;              // b*P1 + p
    int b = bp / P1;
    int p = bp - b * P1;
    int t = threadIdx.x;              // 128 threads
    float y[4];
    #pragma unroll
    for (int j = 0; j < 4; j++) {
        int c = t + j * 128;
        float acc = dw_b[c];
        #pragma unroll
        for (int k = 0; k < 7; k++) {
            int pp = p - 3 + k;
            if (pp >= 0 && pp < SEQ)
                acc += dw_w[k * DIM + c] * g_x[(size_t)(b * SEQ + pp) * DIM + c];
        }
        y[j] = acc;
    }
    float s = y[0]+y[1]+y[2]+y[3];
    float s2 = y[0]*y[0]+y[1]*y[1]+y[2]*y[2]+y[3]*y[3];
    #pragma unroll
    for (int off = 16; off; off >>= 1) {
        s  += __shfl_xor_sync(0xffffffffu, s,  off);
        s2 += __shfl_xor_sync(0xffffffffu, s2, off);
    }
    __shared__ float sh[8];
    int w = t >> 5;
    if ((t & 31) == 0) { sh[w] = s; sh[4 + w] = s2; }
    __syncthreads();
    float S  = sh[0]+sh[1]+sh[2]+sh[3];
    float S2 = sh[4]+sh[5]+sh[6]+sh[7];
    float mean = S * (1.0f/512.0f);
    float var  = S2 * (1.0f/512.0f) - mean * mean;
    float inv  = rsqrtf(var + 1e-6f);
    size_t base = (size_t)(b * MPAD + p) * DIM;
    #pragma unroll
    for (int j = 0; j < 4; j++) {
        int c = t + j * 128;
        float v = (y[j] - mean) * inv * ln_g[c] + ln_b[c];
        __nv_bfloat16 hi = __float2bfloat16_rn(v);
        g_a1h[base + c] = hi;
        g_a1l[base + c] = __float2bfloat16_rn(v - __bfloat162float(hi));
    }
}

// ---------------- GRN finalize: alpha = grn_g * nx + 1 ----------------
__global__ void alpha_kernel(const float* __restrict__ grn_g) {
    int b = blockIdx.x;
    int i = threadIdx.x;              // 1024
    float gx = sqrtf(g_sumsq[b * INTER + i]);
    g_sumsq[b * INTER + i] = 0.0f;    // reset for next layer / next replay
    float r = gx;
    #pragma unroll
    for (int off = 16; off; off >>= 1) r += __shfl_xor_sync(0xffffffffu, r, off);
    __shared__ float sh[32];
    __shared__ float meansh;
    if ((i & 31) == 0) sh[i >> 5] = r;
    __syncthreads();
    if (i < 32) {
        float v = sh[i];
        #pragma unroll
        for (int off = 16; off; off >>= 1) v += __shfl_xor_sync(0xffffffffu, v, off);
        if (i == 0) meansh = v * (1.0f/1024.0f);
    }
    __syncthreads();
    float nx = gx / (meansh + 1e-6f);
    g_alpha[b * INTER + i] = grn_g[i] * nx + 1.0f;
}

// ---------------- GRN transform: A2 = alpha*h + grn_b -> bf16 hi/lo ----------------
__global__ void transform_kernel(const float* __restrict__ grn_b) {
    int row = blockIdx.x;             // 0..4095
    int b = row >> 9;
    const float* h  = g_h + (size_t)row * INTER;
    const float* al = g_alpha + b * INTER;
    __nv_bfloat16* oh = g_a2h + (size_t)row * INTER;
    __nv_bfloat16* ol = g_a2l + (size_t)row * INTER;
    int i = threadIdx.x * 4;          // 256 threads x 4
    float4 hv = *(const float4*)&h[i];
    float4 av = *(const float4*)&al[i];
    float4 gb = *(const float4*)&grn_b[i];
    float v0 = av.x * hv.x + gb.x;
    float v1 = av.y * hv.y + gb.y;
    float v2 = av.z * hv.z + gb.z;
    float v3 = av.w * hv.w + gb.w;
    __nv_bfloat16 h0 = __float2bfloat16_rn(v0), h1 = __float2bfloat16_rn(v1);
    __nv_bfloat16 h2 = __float2bfloat16_rn(v2), h3 = __float2bfloat16_rn(v3);
    __nv_bfloat162 hp0(h0, h1), hp1(h2, h3);
    __nv_bfloat162 lp0(__float2bfloat16_rn(v0 - __bfloat162float(h0)),
                       __float2bfloat16_rn(v1 - __bfloat162float(h1)));
    __nv_bfloat162 lp1(__float2bfloat16_rn(v2 - __bfloat162float(h2)),
                       __float2bfloat16_rn(v3 - __bfloat162float(h3)));
    *(__nv_bfloat162*)&oh[i]     = hp0;
    *(__nv_bfloat162*)&oh[i + 2] = hp1;
    *(__nv_bfloat162*)&ol[i]     = lp0;
    *(__nv_bfloat162*)&ol[i + 2] = lp1;
}

// ---------------- weight transpose + hi/lo split ----------------
__global__ void prep_w(const float* __restrict__ pw1_w, const float* __restrict__ pw2_w) {
    int which = blockIdx.z & 1;
    int l = blockIdx.z >> 1;
    const float* src; __nv_bfloat16 *dh, *dl;
    int R, C;
    if (which == 0) { src = pw1_w + (size_t)l * DIM * INTER; R = DIM;  C = INTER;
                      dh = g_w1h + (size_t)l * INTER * DIM; dl = g_w1l + (size_t)l * INTER * DIM; }
    else            { src = pw2_w + (size_t)l * INTER * DIM; R = INTER; C = DIM;
                      dh = g_w2h + (size_t)l * DIM * INTER; dl = g_w2l + (size_t)l * DIM * INTER; }
    int cx = blockIdx.x * 32, ry = blockIdx.y * 32;
    if (cx >= C || ry >= R) return;
    __shared__ float tl[32][33];
    int tx = threadIdx.x, ty = threadIdx.y;   // (32, 8)
    #pragma unroll
    for (int i = 0; i < 4; i++)
        tl[ty * 4 + i][tx] = src[(size_t)(ry + ty * 4 + i) * C + cx + tx];
    __syncthreads();
    #pragma unroll
    for (int i = 0; i < 4; i++) {
        float w = tl[tx][ty * 4 + i];
        __nv_bfloat16 hi = __float2bfloat16_rn(w);
        size_t o = (size_t)(cx + ty * 4 + i) * R + ry + tx;
        dh[o] = hi;
        dl[o] = __float2bfloat16_rn(w - __bfloat162float(hi));
    }
}

// ---------------- length-regulator upsample ----------------
__global__ void upsample_kernel(const int* __restrict__ seq_len, float* __restrict__ out) {
    int bp = blockIdx.x;
    int b = bp >> 12, p = bp & 4095;
    int al = seq_len[b];
    float4* orow = (float4*)(out + (size_t)bp * DIM);
    if (p >= al) {
        for (int c = threadIdx.x; c < DIM / 4; c += blockDim.x)
            orow[c] = make_float4(0.f, 0.f, 0.f, 0.f);
        return;
    }
    int base  = al >> 9;
    int rem   = al & 511;
    int split = (512 - rem) * base;
    int j = (p < split) ? (p / base) : ((512 - rem) + (p - split) / (base + 1));
    if (j > 511) j = 511;
    const float4* xrow = (const float4*)(g_x + (size_t)(b * SEQ + j) * DIM);
    for (int c = threadIdx.x; c < DIM / 4; c += blockDim.x) orow[c] = xrow[c];
}

// ---------------- launch ----------------
extern "C" void kernel_launch(void* const* d_in, const int* in_sizes, int n_in,
                              void* d_out, int out_size) {
    const int*   text    = (const int*)  d_in[0];
    const int*   seq_len = (const int*)  d_in[1];
    const float* emb     = (const float*)d_in[2];
    const float* dw_w    = (const float*)d_in[3];
    const float* dw_b    = (const float*)d_in[4];
    const float* ln_g    = (const float*)d_in[5];
    const float* ln_b    = (const float*)d_in[6];
    const float* pw1_w   = (const float*)d_in[7];
    const float* pw1_b   = (const float*)d_in[8];
    const float* grn_g   = (const float*)d_in[9];
    const float* grn_b   = (const float*)d_in[10];
    const float* pw2_w   = (const float*)d_in[11];
    const float* pw2_b   = (const float*)d_in[12];
    float* out = (float*)d_out;

    static const int SMEM_BYTES = 64 * 1024;
    cudaFuncSetAttribute(gemm1_mma, cudaFuncAttributeMaxDynamicSharedMemorySize, SMEM_BYTES);
    cudaFuncSetAttribute(gemm2_mma, cudaFuncAttributeMaxDynamicSharedMemorySize, SMEM_BYTES);

    prep_w<<<dim3(32, 32, 2 * NLAYERS), dim3(32, 8)>>>(pw1_w, pw2_w);
    embed_kernel<<<NB * SEQ, 128>>>(text, emb);
    for (int l = 0; l < NLAYERS; l++) {
        convln_kernel<<<NB * P1, 128>>>(dw_w + l * 7 * DIM, dw_b + l * DIM,
                                        ln_g + l * DIM, ln_b + l * DIM);
        gemm1_mma<<<dim3(INTER / 128, NB * MPAD / 128), 256, SMEM_BYTES>>>(l, pw1_b + l * INTER);
        alpha_kernel<<<NB, 1024>>>(grn_g + l * INTER);
        transform_kernel<<<NB * SEQ, 256>>>(grn_b + l * INTER);
        gemm2_mma<<<dim3(DIM / 128, NB * SEQ / 128), 256, SMEM_BYTES>>>(l, pw2_b + l * DIM);
    }
    upsample_kernel<<<NB * MAXSEQ, 128>>>(seq_len, out);
}

// round 4
// speedup vs baseline: 1.9720x; 1.0528x over previous
#include <cuda_runtime.h>
#include <cuda_bf16.h>
#include <math.h>
#include <stdint.h>

#define NB 8
#define SEQ 512
#define MAXSEQ 4096
#define DIM 512
#define INTER 1024
#define NLAYERS 4
#define P1 516
#define MPAD 640
#define CONST_W 3581.0f

// ---------------- scratch ----------------
__device__ float         g_x   [NB*SEQ*DIM];
__device__ __nv_bfloat16 g_a1h [NB*MPAD*DIM];
__device__ __nv_bfloat16 g_a1l [NB*MPAD*DIM];
__device__ float         g_h   [NB*SEQ*INTER];
__device__ __nv_bfloat16 g_a2h [NB*SEQ*INTER];
__device__ __nv_bfloat16 g_a2l [NB*SEQ*INTER];
__device__ __nv_bfloat16 g_w1h [NLAYERS*INTER*DIM];
__device__ __nv_bfloat16 g_w1l [NLAYERS*INTER*DIM];
__device__ __nv_bfloat16 g_w2h [NLAYERS*DIM*INTER];
__device__ __nv_bfloat16 g_w2l [NLAYERS*DIM*INTER];
__device__ float         g_sumsq[NB*INTER];
__device__ float         g_alpha[NB*INTER];

// ---------------- helpers ----------------
__device__ __forceinline__ uint32_t smem_u32(const void* p) {
    uint32_t a;
    asm("{ .reg .u64 t; cvta.to.shared.u64 t, %1; cvt.u32.u64 %0, t; }" : "=r"(a) : "l"(p));
    return a;
}
// swz(row*128 + kb) = row*128 + (kb ^ ((row&7)*16)) for kb < 128
__device__ __forceinline__ uint32_t swz(uint32_t off) {
    return off ^ ((off >> 3) & 0x70u);
}

#define STAGE_BYTES 24576u      // A 16KB + B 8KB
#define NSTAGE 3

// ---------------- stage loader: A 128x64 + B 64x64 bf16 via cp.async ----------------
__device__ __forceinline__ void stage_load(const __nv_bfloat16* Ag, const __nv_bfloat16* Bg,
                                           int K, uint32_t sA, int t) {
    // 1024 A-lines + 512 B-lines of 16B; 256 threads x 6
    #pragma unroll
    for (int i = 0; i < 6; i++) {
        int idx = t + i * 256;
        if (idx < 1024) {
            int row = idx >> 3, kg = idx & 7;
            uint32_t o = (uint32_t)row * 128u + (((uint32_t)kg * 16u) ^ (((uint32_t)row & 7u) * 16u));
            const char* src = (const char*)(Ag + (size_t)row * K) + kg * 16;
            asm volatile("cp.async.cg.shared.global [%0], [%1], 16;" :: "r"(sA + o), "l"(src));
        } else {
            int bidx = idx - 1024;
            int row = bidx >> 3, kg = bidx & 7;
            uint32_t o = 16384u + (uint32_t)row * 128u + (((uint32_t)kg * 16u) ^ (((uint32_t)row & 7u) * 16u));
            const char* src = (const char*)(Bg + (size_t)row * K) + kg * 16;
            asm volatile("cp.async.cg.shared.global [%0], [%1], 16;" :: "r"(sA + o), "l"(src));
        }
    }
}

// ---------------- compute one 64-K stage: warp tile 32x32 ----------------
__device__ __forceinline__ void compute_stage(uint32_t sA,
                                              int warpM, int warpN, int lane,
                                              float acc[2][4][4]) {
    uint32_t sB = sA + 16384u;
    int la = lane & 15, lh = lane >> 4;
    #pragma unroll
    for (int ks = 0; ks < 4; ks++) {
        uint32_t kb = (uint32_t)ks * 32u + (uint32_t)lh * 16u;
        uint32_t a_frag[2][4];
        #pragma unroll
        for (int i = 0; i < 2; i++) {
            uint32_t row = (uint32_t)(warpM * 32 + i * 16 + la);
            uint32_t addr = sA + row * 128u + (kb ^ ((row & 7u) * 16u));
            asm volatile("ldmatrix.sync.aligned.m8n8.x4.shared.b16 {%0,%1,%2,%3}, [%4];"
                : "=r"(a_frag[i][0]), "=r"(a_frag[i][1]), "=r"(a_frag[i][2]), "=r"(a_frag[i][3])
                : "r"(addr));
        }
        uint32_t b_frag[4][2];
        #pragma unroll
        for (int jj = 0; jj < 2; jj++) {
            uint32_t row = (uint32_t)(warpN * 32 + jj * 16 + la);
            uint32_t addr = sB + row * 128u + (kb ^ ((row & 7u) * 16u));
            uint32_t r0, r1, r2, r3;
            asm volatile("ldmatrix.sync.aligned.m8n8.x4.shared.b16 {%0,%1,%2,%3}, [%4];"
                : "=r"(r0), "=r"(r1), "=r"(r2), "=r"(r3) : "r"(addr));
            b_frag[jj*2+0][0] = r0; b_frag[jj*2+0][1] = r2;
            b_frag[jj*2+1][0] = r1; b_frag[jj*2+1][1] = r3;
        }
        #pragma unroll
        for (int i = 0; i < 2; i++)
            #pragma unroll
            for (int j = 0; j < 4; j++)
                asm volatile(
                    "mma.sync.aligned.m16n8k16.row.col.f32.bf16.bf16.f32 "
                    "{%0,%1,%2,%3}, {%4,%5,%6,%7}, {%8,%9}, {%0,%1,%2,%3};"
                    : "+f"(acc[i][j][0]), "+f"(acc[i][j][1]),
                      "+f"(acc[i][j][2]), "+f"(acc[i][j][3])
                    : "r"(a_frag[i][0]), "r"(a_frag[i][1]),
                      "r"(a_frag[i][2]), "r"(a_frag[i][3]),
                      "r"(b_frag[j][0]), "r"(b_frag[j][1]));
    }
}

// ---------------- mainloop: 3-stage pipeline, hi/lo split (3 phases) ----------------
__device__ __forceinline__ void mma_mainloop(
    const __nv_bfloat16* a_hi, const __nv_bfloat16* a_lo,
    const __nv_bfloat16* b_hi, const __nv_bfloat16* b_lo,
    int K, int pc, int m0, int n0,
    uint32_t smem_base, int t, int warpM, int warpN, int lane,
    float acc[2][4][4]) {
    int nchunks = 3 * pc;
    const __nv_bfloat16* Aoff[3] = { a_hi + (size_t)m0 * K, a_lo + (size_t)m0 * K,
                                     a_hi + (size_t)m0 * K };
    const __nv_bfloat16* Boff[3] = { b_hi + (size_t)n0 * K, b_hi + (size_t)n0 * K,
                                     b_lo + (size_t)n0 * K };
    // prefetch stages 0,1
    #pragma unroll
    for (int pf = 0; pf < 2; pf++) {
        int ph = pf / pc, k0 = (pf - ph * pc) * 64;
        stage_load(Aoff[ph] + k0, Boff[ph] + k0, K, smem_base + pf * STAGE_BYTES, t);
        asm volatile("cp.async.commit_group;" ::: "memory");
    }
    int stage = 0;
    for (int kc = 0; kc < nchunks; kc++) {
        asm volatile("cp.async.wait_group 1;" ::: "memory");
        __syncthreads();
        int nk = kc + 2;
        if (nk < nchunks) {
            int ph = nk / pc, k0 = (nk - ph * pc) * 64;
            int ns = nk % NSTAGE;
            stage_load(Aoff[ph] + k0, Boff[ph] + k0, K, smem_base + ns * STAGE_BYTES, t);
        }
        asm volatile("cp.async.commit_group;" ::: "memory");
        compute_stage(smem_base + stage * STAGE_BYTES, warpM, warpN, lane, acc);
        stage = (stage + 1 == NSTAGE) ? 0 : stage + 1;
    }
}

__device__ __forceinline__ float gelu_exact(float v) {
    return 0.5f * v * (1.0f + erff(v * 0.7071067811865476f));
}

// ---------------- GEMM1: h = gelu(A1 @ W1t^T + b), fused GRN sumsq ----------------
__global__ void __launch_bounds__(256, 2) gemm1_mma(int l, const float* __restrict__ bias) {
    extern __shared__ char smem[];
    uint32_t sbase = smem_u32(smem);
    int t = threadIdx.x, lane = t & 31, wid = t >> 5;
    int warpM = wid & 3, warpN = wid >> 2;           // 4 x 2 warps
    int n0 = blockIdx.x * 64, m0 = blockIdx.y * 128;
    float acc[2][4][4] = {};
    mma_mainloop(g_a1h, g_a1l,
                 g_w1h + (size_t)l * INTER * DIM, g_w1l + (size_t)l * INTER * DIM,
                 DIM, 8, m0, n0, sbase, t, warpM, warpN, lane, acc);
    int b  = m0 / MPAD;
    int p0 = m0 - b * MPAD;
    float colsum[4][2] = {};
    #pragma unroll
    for (int i = 0; i < 2; i++) {
        int rowbase = p0 + warpM * 32 + i * 16 + (lane >> 2);
        #pragma unroll
        for (int half = 0; half < 2; half++) {
            int p = rowbase + 8 * half;
            float wgt = (p < 515) ? 1.0f : ((p == 515) ? CONST_W : 0.0f);
            #pragma unroll
            for (int j = 0; j < 4; j++) {
                int n = n0 + warpN * 32 + j * 8 + (lane & 3) * 2;
                float g0 = gelu_exact(acc[i][j][half*2+0] + bias[n]);
                float g1 = gelu_exact(acc[i][j][half*2+1] + bias[n+1]);
                colsum[j][0] += wgt * g0 * g0;
                colsum[j][1] += wgt * g1 * g1;
                if (p < 512) {
                    float2 v2 = make_float2(g0, g1);
                    *(float2*)&g_h[((size_t)(b * SEQ + p)) * INTER + n] = v2;
                }
            }
        }
    }
    #pragma unroll
    for (int j = 0; j < 4; j++)
        #pragma unroll
        for (int s = 0; s < 2; s++) {
            float v = colsum[j][s];
            v += __shfl_xor_sync(0xffffffffu, v, 4);
            v += __shfl_xor_sync(0xffffffffu, v, 8);
            v += __shfl_xor_sync(0xffffffffu, v, 16);
            colsum[j][s] = v;
        }
    if (lane < 4) {
        #pragma unroll
        for (int j = 0; j < 4; j++) {
            int n = n0 + warpN * 32 + j * 8 + lane * 2;
            atomicAdd(&g_sumsq[b * INTER + n],     colsum[j][0]);
            atomicAdd(&g_sumsq[b * INTER + n + 1], colsum[j][1]);
        }
    }
}

// ---------------- GEMM2: x += A2 @ W2t^T + b ----------------
__global__ void __launch_bounds__(256, 2) gemm2_mma(int l, const float* __restrict__ bias) {
    extern __shared__ char smem[];
    uint32_t sbase = smem_u32(smem);
    int t = threadIdx.x, lane = t & 31, wid = t >> 5;
    int warpM = wid & 3, warpN = wid >> 2;
    int n0 = blockIdx.x * 64, m0 = blockIdx.y * 128;
    float acc[2][4][4] = {};
    mma_mainloop(g_a2h, g_a2l,
                 g_w2h + (size_t)l * DIM * INTER, g_w2l + (size_t)l * DIM * INTER,
                 INTER, 16, m0, n0, sbase, t, warpM, warpN, lane, acc);
    #pragma unroll
    for (int i = 0; i < 2; i++) {
        int rowbase = m0 + warpM * 32 + i * 16 + (lane >> 2);
        #pragma unroll
        for (int half = 0; half < 2; half++) {
            int m = rowbase + 8 * half;
            #pragma unroll
            for (int j = 0; j < 4; j++) {
                int n = n0 + warpN * 32 + j * 8 + (lane & 3) * 2;
                size_t xo = (size_t)m * DIM + n;
                float2 xv = *(float2*)&g_x[xo];
                xv.x += acc[i][j][half*2+0] + bias[n];
                xv.y += acc[i][j][half*2+1] + bias[n+1];
                *(float2*)&g_x[xo] = xv;
            }
        }
    }
}

// ---------------- embed + abs pos enc ----------------
__global__ void embed_kernel(const int* __restrict__ text, const float* __restrict__ emb) {
    int bp = blockIdx.x;
    int p = bp & 511, b = bp >> 9;
    int tok = text[b * SEQ + p] + 1;
    const float* erow = emb + (size_t)tok * DIM;
    float* orow = g_x + (size_t)bp * DIM;
    for (int c = threadIdx.x; c < DIM; c += blockDim.x) {
        int i = (c < 256) ? c : (c - 256);
        double f   = exp(-9.210340371976184 * (double)i / 256.0);
        double ang = (double)p * f;
        float pe = (c < 256) ? (float)cos(ang) : (float)sin(ang);
        orow[c] = erow[c] + pe;
    }
}

// ---------------- dwconv(k=7) + LayerNorm -> bf16 hi/lo ----------------
__global__ void convln_kernel(const float* __restrict__ dw_w, const float* __restrict__ dw_b,
                              const float* __restrict__ ln_g, const float* __restrict__ ln_b) {
    int bp = blockIdx.x;
    int b = bp / P1;
    int p = bp - b * P1;
    int t = threadIdx.x;
    float y[4];
    #pragma unroll
    for (int j = 0; j < 4; j++) {
        int c = t + j * 128;
        float acc = dw_b[c];
        #pragma unroll
        for (int k = 0; k < 7; k++) {
            int pp = p - 3 + k;
            if (pp >= 0 && pp < SEQ)
                acc += dw_w[k * DIM + c] * g_x[(size_t)(b * SEQ + pp) * DIM + c];
        }
        y[j] = acc;
    }
    float s = y[0]+y[1]+y[2]+y[3];
    float s2 = y[0]*y[0]+y[1]*y[1]+y[2]*y[2]+y[3]*y[3];
    #pragma unroll
    for (int off = 16; off; off >>= 1) {
        s  += __shfl_xor_sync(0xffffffffu, s,  off);
        s2 += __shfl_xor_sync(0xffffffffu, s2, off);
    }
    __shared__ float sh[8];
    int w = t >> 5;
    if ((t & 31) == 0) { sh[w] = s; sh[4 + w] = s2; }
    __syncthreads();
    float S  = sh[0]+sh[1]+sh[2]+sh[3];
    float S2 = sh[4]+sh[5]+sh[6]+sh[7];
    float mean = S * (1.0f/512.0f);
    float var  = S2 * (1.0f/512.0f) - mean * mean;
    float inv  = rsqrtf(var + 1e-6f);
    size_t base = (size_t)(b * MPAD + p) * DIM;
    #pragma unroll
    for (int j = 0; j < 4; j++) {
        int c = t + j * 128;
        float v = (y[j] - mean) * inv * ln_g[c] + ln_b[c];
        __nv_bfloat16 hi = __float2bfloat16_rn(v);
        g_a1h[base + c] = hi;
        g_a1l[base + c] = __float2bfloat16_rn(v - __bfloat162float(hi));
    }
}

// ---------------- GRN finalize ----------------
__global__ void alpha_kernel(const float* __restrict__ grn_g) {
    int b = blockIdx.x;
    int i = threadIdx.x;
    float gx = sqrtf(g_sumsq[b * INTER + i]);
    g_sumsq[b * INTER + i] = 0.0f;
    float r = gx;
    #pragma unroll
    for (int off = 16; off; off >>= 1) r += __shfl_xor_sync(0xffffffffu, r, off);
    __shared__ float sh[32];
    __shared__ float meansh;
    if ((i & 31) == 0) sh[i >> 5] = r;
    __syncthreads();
    if (i < 32) {
        float v = sh[i];
        #pragma unroll
        for (int off = 16; off; off >>= 1) v += __shfl_xor_sync(0xffffffffu, v, off);
        if (i == 0) meansh = v * (1.0f/1024.0f);
    }
    __syncthreads();
    float nx = gx / (meansh + 1e-6f);
    g_alpha[b * INTER + i] = grn_g[i] * nx + 1.0f;
}

// ---------------- GRN transform ----------------
__global__ void transform_kernel(const float* __restrict__ grn_b) {
    int row = blockIdx.x;
    int b = row >> 9;
    const float* h  = g_h + (size_t)row * INTER;
    const float* al = g_alpha + b * INTER;
    __nv_bfloat16* oh = g_a2h + (size_t)row * INTER;
    __nv_bfloat16* ol = g_a2l + (size_t)row * INTER;
    int i = threadIdx.x * 4;
    float4 hv = *(const float4*)&h[i];
    float4 av = *(const float4*)&al[i];
    float4 gb = *(const float4*)&grn_b[i];
    float v0 = av.x * hv.x + gb.x;
    float v1 = av.y * hv.y + gb.y;
    float v2 = av.z * hv.z + gb.z;
    float v3 = av.w * hv.w + gb.w;
    __nv_bfloat16 h0 = __float2bfloat16_rn(v0), h1 = __float2bfloat16_rn(v1);
    __nv_bfloat16 h2 = __float2bfloat16_rn(v2), h3 = __float2bfloat16_rn(v3);
    __nv_bfloat162 hp0(h0, h1), hp1(h2, h3);
    __nv_bfloat162 lp0(__float2bfloat16_rn(v0 - __bfloat162float(h0)),
                       __float2bfloat16_rn(v1 - __bfloat162float(h1)));
    __nv_bfloat162 lp1(__float2bfloat16_rn(v2 - __bfloat162float(h2)),
                       __float2bfloat16_rn(v3 - __bfloat162float(h3)));
    *(__nv_bfloat162*)&oh[i]     = hp0;
    *(__nv_bfloat162*)&oh[i + 2] = hp1;
    *(__nv_bfloat162*)&ol[i]     = lp0;
    *(__nv_bfloat162*)&ol[i + 2] = lp1;
}

// ---------------- weight transpose + hi/lo split ----------------
__global__ void prep_w(const float* __restrict__ pw1_w, const float* __restrict__ pw2_w) {
    int which = blockIdx.z & 1;
    int l = blockIdx.z >> 1;
    const float* src; __nv_bfloat16 *dh, *dl;
    int R, C;
    if (which == 0) { src = pw1_w + (size_t)l * DIM * INTER; R = DIM;  C = INTER;
                      dh = g_w1h + (size_t)l * INTER * DIM; dl = g_w1l + (size_t)l * INTER * DIM; }
    else            { src = pw2_w + (size_t)l * INTER * DIM; R = INTER; C = DIM;
                      dh = g_w2h + (size_t)l * DIM * INTER; dl = g_w2l + (size_t)l * DIM * INTER; }
    int cx = blockIdx.x * 32, ry = blockIdx.y * 32;
    if (cx >= C || ry >= R) return;
    __shared__ float tl[32][33];
    int tx = threadIdx.x, ty = threadIdx.y;
    #pragma unroll
    for (int i = 0; i < 4; i++)
        tl[ty * 4 + i][tx] = src[(size_t)(ry + ty * 4 + i) * C + cx + tx];
    __syncthreads();
    #pragma unroll
    for (int i = 0; i < 4; i++) {
        float w = tl[tx][ty * 4 + i];
        __nv_bfloat16 hi = __float2bfloat16_rn(w);
        size_t o = (size_t)(cx + ty * 4 + i) * R + ry + tx;
        dh[o] = hi;
        dl[o] = __float2bfloat16_rn(w - __bfloat162float(hi));
    }
}

// ---------------- upsample ----------------
__global__ void upsample_kernel(const int* __restrict__ seq_len, float* __restrict__ out) {
    int bp = blockIdx.x;
    int b = bp >> 12, p = bp & 4095;
    int al = seq_len[b];
    float4* orow = (float4*)(out + (size_t)bp * DIM);
    if (p >= al) {
        for (int c = threadIdx.x; c < DIM / 4; c += blockDim.x)
            orow[c] = make_float4(0.f, 0.f, 0.f, 0.f);
        return;
    }
    int base  = al >> 9;
    int rem   = al & 511;
    int split = (512 - rem) * base;
    int j = (p < split) ? (p / base) : ((512 - rem) + (p - split) / (base + 1));
    if (j > 511) j = 511;
    const float4* xrow = (const float4*)(g_x + (size_t)(b * SEQ + j) * DIM);
    for (int c = threadIdx.x; c < DIM / 4; c += blockDim.x) orow[c] = xrow[c];
}

// ---------------- launch ----------------
extern "C" void kernel_launch(void* const* d_in, const int* in_sizes, int n_in,
                              void* d_out, int out_size) {
    const int*   text    = (const int*)  d_in[0];
    const int*   seq_len = (const int*)  d_in[1];
    const float* emb     = (const float*)d_in[2];
    const float* dw_w    = (const float*)d_in[3];
    const float* dw_b    = (const float*)d_in[4];
    const float* ln_g    = (const float*)d_in[5];
    const float* ln_b    = (const float*)d_in[6];
    const float* pw1_w   = (const float*)d_in[7];
    const float* pw1_b   = (const float*)d_in[8];
    const float* grn_g   = (const float*)d_in[9];
    const float* grn_b   = (const float*)d_in[10];
    const float* pw2_w   = (const float*)d_in[11];
    const float* pw2_b   = (const float*)d_in[12];
    float* out = (float*)d_out;

    static const int SMEM_BYTES = NSTAGE * (int)STAGE_BYTES;  // 72 KB
    cudaFuncSetAttribute(gemm1_mma, cudaFuncAttributeMaxDynamicSharedMemorySize, SMEM_BYTES);
    cudaFuncSetAttribute(gemm2_mma, cudaFuncAttributeMaxDynamicSharedMemorySize, SMEM_BYTES);

    prep_w<<<dim3(32, 32, 2 * NLAYERS), dim3(32, 8)>>>(pw1_w, pw2_w);
    embed_kernel<<<NB * SEQ, 128>>>(text, emb);
    for (int l = 0; l < NLAYERS; l++) {
        convln_kernel<<<NB * P1, 128>>>(dw_w + l * 7 * DIM, dw_b + l * DIM,
                                        ln_g + l * DIM, ln_b + l * DIM);
        gemm1_mma<<<dim3(INTER / 64, NB * MPAD / 128), 256, SMEM_BYTES>>>(l, pw1_b + l * INTER);
        alpha_kernel<<<NB, 1024>>>(grn_g + l * INTER);
        transform_kernel<<<NB * SEQ, 256>>>(grn_b + l * INTER);
        gemm2_mma<<<dim3(DIM / 64, NB * SEQ / 128), 256, SMEM_BYTES>>>(l, pw2_b + l * DIM);
    }
    upsample_kernel<<<NB * MAXSEQ, 128>>>(seq_len, out);
}

// round 5
// speedup vs baseline: 1.9820x; 1.0051x over previous
#include <cuda_runtime.h>
#include <cuda_bf16.h>
#include <math.h>
#include <stdint.h>

#define NB 8
#define SEQ 512
#define MAXSEQ 4096
#define DIM 512
#define INTER 1024
#define NLAYERS 4
#define P1 516
#define MPAD 640
#define CONST_W 3581.0f

// ---------------- scratch ----------------
__device__ float         g_x   [NB*SEQ*DIM];
__device__ __nv_bfloat16 g_a1h [NB*MPAD*DIM];
__device__ __nv_bfloat16 g_a1l [NB*MPAD*DIM];
__device__ float         g_h   [NB*SEQ*INTER];
__device__ __nv_bfloat16 g_a2h [NB*SEQ*INTER];
__device__ __nv_bfloat16 g_a2l [NB*SEQ*INTER];
__device__ __nv_bfloat16 g_w1h [NLAYERS*INTER*DIM];
__device__ __nv_bfloat16 g_w1l [NLAYERS*INTER*DIM];
__device__ __nv_bfloat16 g_w2h [NLAYERS*DIM*INTER];
__device__ __nv_bfloat16 g_w2l [NLAYERS*DIM*INTER];
__device__ float         g_sumsq[NB*INTER];
__device__ float         g_alpha[NB*INTER];

// ---------------- helpers ----------------
__device__ __forceinline__ uint32_t smem_u32(const void* p) {
    uint32_t a;
    asm("{ .reg .u64 t; cvta.to.shared.u64 t, %1; cvt.u32.u64 %0, t; }" : "=r"(a) : "l"(p));
    return a;
}

#define STAGE_BYTES 32768u      // A 16KB + B 16KB
#define NSTAGE 3

// ---------------- stage loader: A 128x64 + B 128x64 bf16, branch-free ----------------
__device__ __forceinline__ void stage_load(const __nv_bfloat16* Ag, const __nv_bfloat16* Bg,
                                           int K, uint32_t sA, int t) {
    #pragma unroll
    for (int i = 0; i < 4; i++) {
        int idx = t + i * 256;                 // 0..1023
        int row = idx >> 3, kg = idx & 7;
        uint32_t o = (uint32_t)row * 128u + (((uint32_t)kg * 16u) ^ (((uint32_t)row & 7u) * 16u));
        const char* srcA = (const char*)(Ag + (size_t)row * K) + kg * 16;
        asm volatile("cp.async.cg.shared.global [%0], [%1], 16;" :: "r"(sA + o), "l"(srcA));
        const char* srcB = (const char*)(Bg + (size_t)row * K) + kg * 16;
        asm volatile("cp.async.cg.shared.global [%0], [%1], 16;" :: "r"(sA + 16384u + o), "l"(srcB));
    }
}

// ---------------- compute one 64-K stage: warp tile 64x32 ----------------
__device__ __forceinline__ void compute_stage(uint32_t sA,
                                              int warpM, int warpN, int lane,
                                              float acc[4][4][4]) {
    int la = lane & 15, lh = lane >> 4;
    uint32_t aaddr[4], baddr[2];
    #pragma unroll
    for (int i = 0; i < 4; i++) {
        uint32_t row = (uint32_t)(warpM * 64 + i * 16 + la);
        aaddr[i] = sA + row * 128u + (((uint32_t)lh * 16u) ^ ((row & 7u) * 16u));
    }
    #pragma unroll
    for (int jj = 0; jj < 2; jj++) {
        uint32_t row = (uint32_t)(warpN * 32 + jj * 16 + la);
        baddr[jj] = sA + 16384u + row * 128u + (((uint32_t)lh * 16u) ^ ((row & 7u) * 16u));
    }
    #pragma unroll
    for (int ks = 0; ks < 4; ks++) {
        uint32_t kx = (uint32_t)ks * 32u;
        uint32_t a_frag[4][4];
        #pragma unroll
        for (int i = 0; i < 4; i++)
            asm volatile("ldmatrix.sync.aligned.m8n8.x4.shared.b16 {%0,%1,%2,%3}, [%4];"
                : "=r"(a_frag[i][0]), "=r"(a_frag[i][1]), "=r"(a_frag[i][2]), "=r"(a_frag[i][3])
                : "r"(aaddr[i] ^ kx));
        uint32_t b_frag[4][2];
        #pragma unroll
        for (int jj = 0; jj < 2; jj++) {
            uint32_t r0, r1, r2, r3;
            asm volatile("ldmatrix.sync.aligned.m8n8.x4.shared.b16 {%0,%1,%2,%3}, [%4];"
                : "=r"(r0), "=r"(r1), "=r"(r2), "=r"(r3) : "r"(baddr[jj] ^ kx));
            b_frag[jj*2+0][0] = r0; b_frag[jj*2+0][1] = r2;
            b_frag[jj*2+1][0] = r1; b_frag[jj*2+1][1] = r3;
        }
        #pragma unroll
        for (int i = 0; i < 4; i++)
            #pragma unroll
            for (int j = 0; j < 4; j++)
                asm volatile(
                    "mma.sync.aligned.m16n8k16.row.col.f32.bf16.bf16.f32 "
                    "{%0,%1,%2,%3}, {%4,%5,%6,%7}, {%8,%9}, {%0,%1,%2,%3};"
                    : "+f"(acc[i][j][0]), "+f"(acc[i][j][1]),
                      "+f"(acc[i][j][2]), "+f"(acc[i][j][3])
                    : "r"(a_frag[i][0]), "r"(a_frag[i][1]),
                      "r"(a_frag[i][2]), "r"(a_frag[i][3]),
                      "r"(b_frag[j][0]), "r"(b_frag[j][1]));
    }
}

// ---------------- mainloop over chunk range [c0, c1) ----------------
__device__ __forceinline__ void mma_mainloop(
    const __nv_bfloat16* a_hi, const __nv_bfloat16* a_lo,
    const __nv_bfloat16* b_hi, const __nv_bfloat16* b_lo,
    int K, int pc, int c0, int c1, int m0, int n0,
    uint32_t smem_base, int t, int warpM, int warpN, int lane,
    float acc[4][4][4]) {
    const __nv_bfloat16* Aoff[3] = { a_hi + (size_t)m0 * K, a_lo + (size_t)m0 * K,
                                     a_hi + (size_t)m0 * K };
    const __nv_bfloat16* Boff[3] = { b_hi + (size_t)n0 * K, b_hi + (size_t)n0 * K,
                                     b_lo + (size_t)n0 * K };
    #pragma unroll
    for (int pf = 0; pf < 2; pf++) {
        int c = c0 + pf;
        int ph = c / pc, k0 = (c - ph * pc) * 64;
        stage_load(Aoff[ph] + k0, Boff[ph] + k0, K, smem_base + pf * STAGE_BYTES, t);
        asm volatile("cp.async.commit_group;" ::: "memory");
    }
    int stage = 0;
    for (int kc = c0; kc < c1; kc++) {
        asm volatile("cp.async.wait_group 1;" ::: "memory");
        __syncthreads();
        int nk = kc + 2;
        if (nk < c1) {
            int ph = nk / pc, k0 = (nk - ph * pc) * 64;
            int ns = (nk - c0) % NSTAGE;
            stage_load(Aoff[ph] + k0, Boff[ph] + k0, K, smem_base + ns * STAGE_BYTES, t);
        }
        asm volatile("cp.async.commit_group;" ::: "memory");
        compute_stage(smem_base + stage * STAGE_BYTES, warpM, warpN, lane, acc);
        stage = (stage + 1 == NSTAGE) ? 0 : stage + 1;
    }
}

__device__ __forceinline__ float gelu_exact(float v) {
    return 0.5f * v * (1.0f + erff(v * 0.7071067811865476f));
}

// ---------------- GEMM1: h = gelu(A1 @ W1t^T + b), fused GRN sumsq ----------------
__global__ void __launch_bounds__(256, 2) gemm1_mma(int l, const float* __restrict__ bias) {
    extern __shared__ char smem[];
    uint32_t sbase = smem_u32(smem);
    int t = threadIdx.x, lane = t & 31, wid = t >> 5;
    int warpM = wid & 1, warpN = wid >> 1;           // 2M x 4N warps (64x32 tiles)
    int n0 = blockIdx.x * 128, m0 = blockIdx.y * 128;
    float acc[4][4][4] = {};
    mma_mainloop(g_a1h, g_a1l,
                 g_w1h + (size_t)l * INTER * DIM, g_w1l + (size_t)l * INTER * DIM,
                 DIM, 8, 0, 24, m0, n0, sbase, t, warpM, warpN, lane, acc);
    int b  = m0 / MPAD;
    int p0 = m0 - b * MPAD;
    float colsum[4][2] = {};
    #pragma unroll
    for (int i = 0; i < 4; i++) {
        int rowbase = p0 + warpM * 64 + i * 16 + (lane >> 2);
        #pragma unroll
        for (int half = 0; half < 2; half++) {
            int p = rowbase + 8 * half;
            float wgt = (p < 515) ? 1.0f : ((p == 515) ? CONST_W : 0.0f);
            #pragma unroll
            for (int j = 0; j < 4; j++) {
                int n = n0 + warpN * 32 + j * 8 + (lane & 3) * 2;
                float g0 = gelu_exact(acc[i][j][half*2+0] + bias[n]);
                float g1 = gelu_exact(acc[i][j][half*2+1] + bias[n+1]);
                colsum[j][0] += wgt * g0 * g0;
                colsum[j][1] += wgt * g1 * g1;
                if (p < 512) {
                    float2 v2 = make_float2(g0, g1);
                    *(float2*)&g_h[((size_t)(b * SEQ + p)) * INTER + n] = v2;
                }
            }
        }
    }
    #pragma unroll
    for (int j = 0; j < 4; j++)
        #pragma unroll
        for (int s = 0; s < 2; s++) {
            float v = colsum[j][s];
            v += __shfl_xor_sync(0xffffffffu, v, 4);
            v += __shfl_xor_sync(0xffffffffu, v, 8);
            v += __shfl_xor_sync(0xffffffffu, v, 16);
            colsum[j][s] = v;
        }
    if (lane < 4) {
        #pragma unroll
        for (int j = 0; j < 4; j++) {
            int n = n0 + warpN * 32 + j * 8 + lane * 2;
            atomicAdd(&g_sumsq[b * INTER + n],     colsum[j][0]);
            atomicAdd(&g_sumsq[b * INTER + n + 1], colsum[j][1]);
        }
    }
}

// ---------------- GEMM2: x += A2 @ W2t^T + b  (K-split 2, atomic epilogue) ----------------
__global__ void __launch_bounds__(256, 2) gemm2_mma(int l, const float* __restrict__ bias) {
    extern __shared__ char smem[];
    uint32_t sbase = smem_u32(smem);
    int t = threadIdx.x, lane = t & 31, wid = t >> 5;
    int warpM = wid & 1, warpN = wid >> 1;
    int n0 = blockIdx.x * 128, m0 = blockIdx.y * 128;
    int split = blockIdx.z;
    float acc[4][4][4] = {};
    mma_mainloop(g_a2h, g_a2l,
                 g_w2h + (size_t)l * DIM * INTER, g_w2l + (size_t)l * DIM * INTER,
                 INTER, 16, split * 24, split * 24 + 24, m0, n0,
                 sbase, t, warpM, warpN, lane, acc);
    #pragma unroll
    for (int i = 0; i < 4; i++) {
        int rowbase = m0 + warpM * 64 + i * 16 + (lane >> 2);
        #pragma unroll
        for (int half = 0; half < 2; half++) {
            int m = rowbase + 8 * half;
            #pragma unroll
            for (int j = 0; j < 4; j++) {
                int n = n0 + warpN * 32 + j * 8 + (lane & 3) * 2;
                size_t xo = (size_t)m * DIM + n;
                float add0 = acc[i][j][half*2+0];
                float add1 = acc[i][j][half*2+1];
                if (split == 0) { add0 += bias[n]; add1 += bias[n+1]; }
                atomicAdd(&g_x[xo],     add0);
                atomicAdd(&g_x[xo + 1], add1);
            }
        }
    }
}

// ---------------- embed + abs pos enc ----------------
__global__ void embed_kernel(const int* __restrict__ text, const float* __restrict__ emb) {
    int bp = blockIdx.x;
    int p = bp & 511, b = bp >> 9;
    int tok = text[b * SEQ + p] + 1;
    const float* erow = emb + (size_t)tok * DIM;
    float* orow = g_x + (size_t)bp * DIM;
    for (int c = threadIdx.x; c < DIM; c += blockDim.x) {
        int i = (c < 256) ? c : (c - 256);
        double f   = exp(-9.210340371976184 * (double)i / 256.0);
        double ang = (double)p * f;
        float pe = (c < 256) ? (float)cos(ang) : (float)sin(ang);
        orow[c] = erow[c] + pe;
    }
}

// ---------------- dwconv(k=7) + LayerNorm -> bf16 hi/lo ----------------
__global__ void convln_kernel(const float* __restrict__ dw_w, const float* __restrict__ dw_b,
                              const float* __restrict__ ln_g, const float* __restrict__ ln_b) {
    int bp = blockIdx.x;
    int b = bp / P1;
    int p = bp - b * P1;
    int t = threadIdx.x;
    float y[4];
    #pragma unroll
    for (int j = 0; j < 4; j++) {
        int c = t + j * 128;
        float acc = dw_b[c];
        #pragma unroll
        for (int k = 0; k < 7; k++) {
            int pp = p - 3 + k;
            if (pp >= 0 && pp < SEQ)
                acc += dw_w[k * DIM + c] * g_x[(size_t)(b * SEQ + pp) * DIM + c];
        }
        y[j] = acc;
    }
    float s = y[0]+y[1]+y[2]+y[3];
    float s2 = y[0]*y[0]+y[1]*y[1]+y[2]*y[2]+y[3]*y[3];
    #pragma unroll
    for (int off = 16; off; off >>= 1) {
        s  += __shfl_xor_sync(0xffffffffu, s,  off);
        s2 += __shfl_xor_sync(0xffffffffu, s2, off);
    }
    __shared__ float sh[8];
    int w = t >> 5;
    if ((t & 31) == 0) { sh[w] = s; sh[4 + w] = s2; }
    __syncthreads();
    float S  = sh[0]+sh[1]+sh[2]+sh[3];
    float S2 = sh[4]+sh[5]+sh[6]+sh[7];
    float mean = S * (1.0f/512.0f);
    float var  = S2 * (1.0f/512.0f) - mean * mean;
    float inv  = rsqrtf(var + 1e-6f);
    size_t base = (size_t)(b * MPAD + p) * DIM;
    #pragma unroll
    for (int j = 0; j < 4; j++) {
        int c = t + j * 128;
        float v = (y[j] - mean) * inv * ln_g[c] + ln_b[c];
        __nv_bfloat16 hi = __float2bfloat16_rn(v);
        g_a1h[base + c] = hi;
        g_a1l[base + c] = __float2bfloat16_rn(v - __bfloat162float(hi));
    }
}

// ---------------- GRN finalize ----------------
__global__ void alpha_kernel(const float* __restrict__ grn_g) {
    int b = blockIdx.x;
    int i = threadIdx.x;
    float gx = sqrtf(g_sumsq[b * INTER + i]);
    g_sumsq[b * INTER + i] = 0.0f;
    float r = gx;
    #pragma unroll
    for (int off = 16; off; off >>= 1) r += __shfl_xor_sync(0xffffffffu, r, off);
    __shared__ float sh[32];
    __shared__ float meansh;
    if ((i & 31) == 0) sh[i >> 5] = r;
    __syncthreads();
    if (i < 32) {
        float v = sh[i];
        #pragma unroll
        for (int off = 16; off; off >>= 1) v += __shfl_xor_sync(0xffffffffu, v, off);
        if (i == 0) meansh = v * (1.0f/1024.0f);
    }
    __syncthreads();
    float nx = gx / (meansh + 1e-6f);
    g_alpha[b * INTER + i] = grn_g[i] * nx + 1.0f;
}

// ---------------- GRN transform ----------------
__global__ void transform_kernel(const float* __restrict__ grn_b) {
    int row = blockIdx.x;
    int b = row >> 9;
    const float* h  = g_h + (size_t)row * INTER;
    const float* al = g_alpha + b * INTER;
    __nv_bfloat16* oh = g_a2h + (size_t)row * INTER;
    __nv_bfloat16* ol = g_a2l + (size_t)row * INTER;
    int i = threadIdx.x * 4;
    float4 hv = *(const float4*)&h[i];
    float4 av = *(const float4*)&al[i];
    float4 gb = *(const float4*)&grn_b[i];
    float v0 = av.x * hv.x + gb.x;
    float v1 = av.y * hv.y + gb.y;
    float v2 = av.z * hv.z + gb.z;
    float v3 = av.w * hv.w + gb.w;
    __nv_bfloat16 h0 = __float2bfloat16_rn(v0), h1 = __float2bfloat16_rn(v1);
    __nv_bfloat16 h2 = __float2bfloat16_rn(v2), h3 = __float2bfloat16_rn(v3);
    __nv_bfloat162 hp0(h0, h1), hp1(h2, h3);
    __nv_bfloat162 lp0(__float2bfloat16_rn(v0 - __bfloat162float(h0)),
                       __float2bfloat16_rn(v1 - __bfloat162float(h1)));
    __nv_bfloat162 lp1(__float2bfloat16_rn(v2 - __bfloat162float(h2)),
                       __float2bfloat16_rn(v3 - __bfloat162float(h3)));
    *(__nv_bfloat162*)&oh[i]     = hp0;
    *(__nv_bfloat162*)&oh[i + 2] = hp1;
    *(__nv_bfloat162*)&ol[i]     = lp0;
    *(__nv_bfloat162*)&ol[i + 2] = lp1;
}

// ---------------- weight transpose + hi/lo split ----------------
__global__ void prep_w(const float* __restrict__ pw1_w, const float* __restrict__ pw2_w) {
    int which = blockIdx.z & 1;
    int l = blockIdx.z >> 1;
    const float* src; __nv_bfloat16 *dh, *dl;
    int R, C;
    if (which == 0) { src = pw1_w + (size_t)l * DIM * INTER; R = DIM;  C = INTER;
                      dh = g_w1h + (size_t)l * INTER * DIM; dl = g_w1l + (size_t)l * INTER * DIM; }
    else            { src = pw2_w + (size_t)l * INTER * DIM; R = INTER; C = DIM;
                      dh = g_w2h + (size_t)l * DIM * INTER; dl = g_w2l + (size_t)l * DIM * INTER; }
    int cx = blockIdx.x * 32, ry = blockIdx.y * 32;
    if (cx >= C || ry >= R) return;
    __shared__ float tl[32][33];
    int tx = threadIdx.x, ty = threadIdx.y;
    #pragma unroll
    for (int i = 0; i < 4; i++)
        tl[ty * 4 + i][tx] = src[(size_t)(ry + ty * 4 + i) * C + cx + tx];
    __syncthreads();
    #pragma unroll
    for (int i = 0; i < 4; i++) {
        float w = tl[tx][ty * 4 + i];
        __nv_bfloat16 hi = __float2bfloat16_rn(w);
        size_t o = (size_t)(cx + ty * 4 + i) * R + ry + tx;
        dh[o] = hi;
        dl[o] = __float2bfloat16_rn(w - __bfloat162float(hi));
    }
}

// ---------------- upsample ----------------
__global__ void upsample_kernel(const int* __restrict__ seq_len, float* __restrict__ out) {
    int bp = blockIdx.x;
    int b = bp >> 12, p = bp & 4095;
    int al = seq_len[b];
    float4* orow = (float4*)(out + (size_t)bp * DIM);
    if (p >= al) {
        for (int c = threadIdx.x; c < DIM / 4; c += blockDim.x)
            orow[c] = make_float4(0.f, 0.f, 0.f, 0.f);
        return;
    }
    int base  = al >> 9;
    int rem   = al & 511;
    int split = (512 - rem) * base;
    int j = (p < split) ? (p / base) : ((512 - rem) + (p - split) / (base + 1));
    if (j > 511) j = 511;
    const float4* xrow = (const float4*)(g_x + (size_t)(b * SEQ + j) * DIM);
    for (int c = threadIdx.x; c < DIM / 4; c += blockDim.x) orow[c] = xrow[c];
}

// ---------------- launch ----------------
extern "C" void kernel_launch(void* const* d_in, const int* in_sizes, int n_in,
                              void* d_out, int out_size) {
    const int*   text    = (const int*)  d_in[0];
    const int*   seq_len = (const int*)  d_in[1];
    const float* emb     = (const float*)d_in[2];
    const float* dw_w    = (const float*)d_in[3];
    const float* dw_b    = (const float*)d_in[4];
    const float* ln_g    = (const float*)d_in[5];
    const float* ln_b    = (const float*)d_in[6];
    const float* pw1_w   = (const float*)d_in[7];
    const float* pw1_b   = (const float*)d_in[8];
    const float* grn_g   = (const float*)d_in[9];
    const float* grn_b   = (const float*)d_in[10];
    const float* pw2_w   = (const float*)d_in[11];
    const float* pw2_b   = (const float*)d_in[12];
    float* out = (float*)d_out;

    static const int SMEM_BYTES = NSTAGE * (int)STAGE_BYTES;  // 96 KB
    cudaFuncSetAttribute(gemm1_mma, cudaFuncAttributeMaxDynamicSharedMemorySize, SMEM_BYTES);
    cudaFuncSetAttribute(gemm2_mma, cudaFuncAttributeMaxDynamicSharedMemorySize, SMEM_BYTES);

    prep_w<<<dim3(32, 32, 2 * NLAYERS), dim3(32, 8)>>>(pw1_w, pw2_w);
    embed_kernel<<<NB * SEQ, 128>>>(text, emb);
    for (int l = 0; l < NLAYERS; l++) {
        convln_kernel<<<NB * P1, 128>>>(dw_w + l * 7 * DIM, dw_b + l * DIM,
                                        ln_g + l * DIM, ln_b + l * DIM);
        gemm1_mma<<<dim3(INTER / 128, NB * MPAD / 128), 256, SMEM_BYTES>>>(l, pw1_b + l * INTER);
        alpha_kernel<<<NB, 1024>>>(grn_g + l * INTER);
        transform_kernel<<<NB * SEQ, 256>>>(grn_b + l * INTER);
        gemm2_mma<<<dim3(DIM / 128, NB * SEQ / 128, 2), 256, SMEM_BYTES>>>(l, pw2_b + l * DIM);
    }
    upsample_kernel<<<NB * MAXSEQ, 128>>>(seq_len, out);
}

// round 6
// speedup vs baseline: 2.1500x; 1.0847x over previous
#include <cuda_runtime.h>
#include <cuda_bf16.h>
#include <math.h>
#include <stdint.h>

#define NB 8
#define SEQ 512
#define MAXSEQ 4096
#define DIM 512
#define INTER 1024
#define NLAYERS 4
#define P1 516
#define M1 (NB*P1)            // 4128 gemm1 rows (packed)
#define M1T 33                // ceil(4128/128)
#define CONST_W 3581.0f

// ---------------- scratch ----------------
__device__ float         g_x   [NB*SEQ*DIM];
__device__ __nv_bfloat16 g_a1h [(M1T*128)*DIM];       // rows >= 4128 stay zero
__device__ __nv_bfloat16 g_a1l [(M1T*128)*DIM];
__device__ float         g_h   [(M1T*128)*INTER];     // packed rows b*516+p
__device__ __nv_bfloat16 g_a2h [NB*SEQ*INTER];
__device__ __nv_bfloat16 g_a2l [NB*SEQ*INTER];
__device__ __nv_bfloat16 g_w1h [NLAYERS*INTER*DIM];
__device__ __nv_bfloat16 g_w1l [NLAYERS*INTER*DIM];
__device__ __nv_bfloat16 g_w2h [NLAYERS*DIM*INTER];
__device__ __nv_bfloat16 g_w2l [NLAYERS*DIM*INTER];
__device__ float         g_sumsq[NB*INTER];
__device__ float         g_alpha[NB*INTER];

// ---------------- helpers ----------------
__device__ __forceinline__ uint32_t smem_u32(const void* p) {
    uint32_t a;
    asm("{ .reg .u64 t; cvta.to.shared.u64 t, %1; cvt.u32.u64 %0, t; }" : "=r"(a) : "l"(p));
    return a;
}

#define STAGE_BYTES 32768u      // A 16KB + B 16KB
#define NSTAGE 3

// ---------------- compute one 64-K stage: warp tile 64x32 ----------------
__device__ __forceinline__ void compute_stage(uint32_t sbs,
                                              const uint32_t aoff[4], const uint32_t boff2[2],
                                              float acc[4][4][4]) {
    #pragma unroll
    for (int ks = 0; ks < 4; ks++) {
        uint32_t kx = (uint32_t)ks * 32u;
        uint32_t a_frag[4][4];
        #pragma unroll
        for (int i = 0; i < 4; i++)
            asm volatile("ldmatrix.sync.aligned.m8n8.x4.shared.b16 {%0,%1,%2,%3}, [%4];"
                : "=r"(a_frag[i][0]), "=r"(a_frag[i][1]), "=r"(a_frag[i][2]), "=r"(a_frag[i][3])
                : "r"((sbs + aoff[i]) ^ kx));
        uint32_t b_frag[4][2];
        #pragma unroll
        for (int jj = 0; jj < 2; jj++) {
            uint32_t r0, r1, r2, r3;
            asm volatile("ldmatrix.sync.aligned.m8n8.x4.shared.b16 {%0,%1,%2,%3}, [%4];"
                : "=r"(r0), "=r"(r1), "=r"(r2), "=r"(r3) : "r"((sbs + boff2[jj]) ^ kx));
            b_frag[jj*2+0][0] = r0; b_frag[jj*2+0][1] = r2;
            b_frag[jj*2+1][0] = r1; b_frag[jj*2+1][1] = r3;
        }
        #pragma unroll
        for (int i = 0; i < 4; i++)
            #pragma unroll
            for (int j = 0; j < 4; j++)
                asm volatile(
                    "mma.sync.aligned.m16n8k16.row.col.f32.bf16.bf16.f32 "
                    "{%0,%1,%2,%3}, {%4,%5,%6,%7}, {%8,%9}, {%0,%1,%2,%3};"
                    : "+f"(acc[i][j][0]), "+f"(acc[i][j][1]),
                      "+f"(acc[i][j][2]), "+f"(acc[i][j][3])
                    : "r"(a_frag[i][0]), "r"(a_frag[i][1]),
                      "r"(a_frag[i][2]), "r"(a_frag[i][3]),
                      "r"(b_frag[j][0]), "r"(b_frag[j][1]));
    }
}

// ---------------- mainloop over chunk range [c0, c1) ----------------
__device__ __forceinline__ void mma_mainloop(
    const __nv_bfloat16* a_hi, const __nv_bfloat16* a_lo,
    const __nv_bfloat16* b_hi, const __nv_bfloat16* b_lo,
    int K, int pc, int c0, int c1, int m0, int n0,
    uint32_t smem_base, int t, int warpM, int warpN, int lane,
    float acc[4][4][4]) {
    // per-thread cp.async offsets (constant over chunks)
    int lrow = t >> 3, lkg = t & 7;
    uint32_t so = (uint32_t)lrow * 128u + (((uint32_t)lkg * 16u) ^ (((uint32_t)lrow & 7u) * 16u));
    size_t srcoff = (size_t)lrow * K + lkg * 8;
    size_t rbytes = (size_t)32 * K * 2;           // 32 rows, bytes

    const __nv_bfloat16* A0 = a_hi + (size_t)m0 * K + srcoff;
    const __nv_bfloat16* A1 = a_lo + (size_t)m0 * K + srcoff;
    const __nv_bfloat16* B0 = b_hi + (size_t)n0 * K + srcoff;
    const __nv_bfloat16* B2 = b_lo + (size_t)n0 * K + srcoff;

    int ph = c0 / pc;                             // entry phase: 0 or 1
    int kk = c0 - ph * pc;
    const __nv_bfloat16* pA = ((ph == 1) ? A1 : A0) + (size_t)kk * 64;
    const __nv_bfloat16* pB = B0 + (size_t)kk * 64;

    // ldmatrix offsets (constant over chunks)
    int la = lane & 15, lh = lane >> 4;
    uint32_t aoff[4], boff2[2];
    #pragma unroll
    for (int i = 0; i < 4; i++) {
        uint32_t row = (uint32_t)(warpM * 64 + i * 16 + la);
        aoff[i] = row * 128u + (((uint32_t)lh * 16u) ^ ((row & 7u) * 16u));
    }
    #pragma unroll
    for (int jj = 0; jj < 2; jj++) {
        uint32_t row = (uint32_t)(warpN * 32 + jj * 16 + la);
        boff2[jj] = 16384u + row * 128u + (((uint32_t)lh * 16u) ^ ((row & 7u) * 16u));
    }

#define ISSUE(slot) do { \
    uint32_t dst = smem_base + (uint32_t)(slot) * STAGE_BYTES; \
    const char* sa = (const char*)pA; const char* sb = (const char*)pB; \
    _Pragma("unroll") \
    for (int ii = 0; ii < 4; ii++) { \
        asm volatile("cp.async.cg.shared.global [%0], [%1], 16;" \
                     :: "r"(dst + so + (uint32_t)ii * 4096u), "l"(sa)); \
        asm volatile("cp.async.cg.shared.global [%0], [%1], 16;" \
                     :: "r"(dst + 16384u + so + (uint32_t)ii * 4096u), "l"(sb)); \
        sa += rbytes; sb += rbytes; } } while(0)

#define ADV() do { pA += 64; pB += 64; \
    if (++kk == pc) { kk = 0; ph++; \
        if (ph == 1) { pA = A1; pB = B0; } \
        else if (ph == 2) { pA = A0; pB = B2; } } } while(0)

    ISSUE(0); asm volatile("cp.async.commit_group;" ::: "memory"); ADV();
    ISSUE(1); asm volatile("cp.async.commit_group;" ::: "memory"); ADV();
    int stage = 0, pf_slot = 2;
    for (int kc = c0; kc < c1; kc++) {
        asm volatile("cp.async.wait_group 1;" ::: "memory");
        __syncthreads();
        if (kc + 2 < c1) {
            ISSUE(pf_slot); ADV();
            pf_slot = (pf_slot + 1 == NSTAGE) ? 0 : pf_slot + 1;
        }
        asm volatile("cp.async.commit_group;" ::: "memory");
        compute_stage(smem_base + (uint32_t)stage * STAGE_BYTES, aoff, boff2, acc);
        stage = (stage + 1 == NSTAGE) ? 0 : stage + 1;
    }
#undef ISSUE
#undef ADV
}

__device__ __forceinline__ float gelu_exact(float v) {
    return 0.5f * v * (1.0f + erff(v * 0.7071067811865476f));
}

// ---------------- GEMM1: h = gelu(A1 @ W1t^T + b) ----------------
__global__ void __launch_bounds__(256, 2) gemm1_mma(int l, const float* __restrict__ bias) {
    extern __shared__ char smem[];
    uint32_t sbase = smem_u32(smem);
    int t = threadIdx.x, lane = t & 31, wid = t >> 5;
    int warpM = wid & 1, warpN = wid >> 1;           // 2M x 4N warps (64x32 tiles)
    int n0 = blockIdx.x * 128, m0 = blockIdx.y * 128;
    float acc[4][4][4] = {};
    mma_mainloop(g_a1h, g_a1l,
                 g_w1h + (size_t)l * INTER * DIM, g_w1l + (size_t)l * INTER * DIM,
                 DIM, 8, 0, 24, m0, n0, sbase, t, warpM, warpN, lane, acc);
    #pragma unroll
    for (int i = 0; i < 4; i++) {
        #pragma unroll
        for (int half = 0; half < 2; half++) {
            int r = m0 + warpM * 64 + i * 16 + (lane >> 2) + 8 * half;
            if (r < M1) {
                #pragma unroll
                for (int j = 0; j < 4; j++) {
                    int n = n0 + warpN * 32 + j * 8 + (lane & 3) * 2;
                    float g0 = gelu_exact(acc[i][j][half*2+0] + bias[n]);
                    float g1 = gelu_exact(acc[i][j][half*2+1] + bias[n+1]);
                    *(float2*)&g_h[(size_t)r * INTER + n] = make_float2(g0, g1);
                }
            }
        }
    }
}

// ---------------- GEMM2: x += A2 @ W2t^T + b  (K-split 2, atomic epilogue) ----------------
__global__ void __launch_bounds__(256, 2) gemm2_mma(int l, const float* __restrict__ bias) {
    extern __shared__ char smem[];
    uint32_t sbase = smem_u32(smem);
    int t = threadIdx.x, lane = t & 31, wid = t >> 5;
    int warpM = wid & 1, warpN = wid >> 1;
    int n0 = blockIdx.x * 128, m0 = blockIdx.y * 128;
    int split = blockIdx.z;
    float acc[4][4][4] = {};
    mma_mainloop(g_a2h, g_a2l,
                 g_w2h + (size_t)l * DIM * INTER, g_w2l + (size_t)l * DIM * INTER,
                 INTER, 16, split * 24, split * 24 + 24, m0, n0,
                 sbase, t, warpM, warpN, lane, acc);
    #pragma unroll
    for (int i = 0; i < 4; i++) {
        int rowbase = m0 + warpM * 64 + i * 16 + (lane >> 2);
        #pragma unroll
        for (int half = 0; half < 2; half++) {
            int m = rowbase + 8 * half;
            #pragma unroll
            for (int j = 0; j < 4; j++) {
                int n = n0 + warpN * 32 + j * 8 + (lane & 3) * 2;
                size_t xo = (size_t)m * DIM + n;
                float add0 = acc[i][j][half*2+0];
                float add1 = acc[i][j][half*2+1];
                if (split == 0) { add0 += bias[n]; add1 += bias[n+1]; }
                atomicAdd(&g_x[xo],     add0);
                atomicAdd(&g_x[xo + 1], add1);
            }
        }
    }
}

// ---------------- embed + abs pos enc (fp32 trig, matches numpy fp32) ----------------
__global__ void embed_kernel(const int* __restrict__ text, const float* __restrict__ emb) {
    int bp = blockIdx.x;
    int p = bp & 511, b = bp >> 9;
    int tok = text[b * SEQ + p] + 1;
    const float* erow = emb + (size_t)tok * DIM;
    float* orow = g_x + (size_t)bp * DIM;
    for (int c = threadIdx.x; c < DIM; c += blockDim.x) {
        int i = (c < 256) ? c : (c - 256);
        float f   = expf(-9.210340371976184f * (float)i / 256.0f);
        float ang = (float)p * f;
        float pe = (c < 256) ? cosf(ang) : sinf(ang);
        orow[c] = erow[c] + pe;
    }
}

// ---------------- dwconv(k=7) + LayerNorm -> bf16 hi/lo (packed rows) ----------------
__global__ void convln_kernel(const float* __restrict__ dw_w, const float* __restrict__ dw_b,
                              const float* __restrict__ ln_g, const float* __restrict__ ln_b) {
    int bp = blockIdx.x;              // b*P1 + p
    int b = bp / P1;
    int p = bp - b * P1;
    int t = threadIdx.x;
    float y[4];
    #pragma unroll
    for (int j = 0; j < 4; j++) {
        int c = t + j * 128;
        float acc = dw_b[c];
        #pragma unroll
        for (int k = 0; k < 7; k++) {
            int pp = p - 3 + k;
            if (pp >= 0 && pp < SEQ)
                acc += dw_w[k * DIM + c] * g_x[(size_t)(b * SEQ + pp) * DIM + c];
        }
        y[j] = acc;
    }
    float s = y[0]+y[1]+y[2]+y[3];
    float s2 = y[0]*y[0]+y[1]*y[1]+y[2]*y[2]+y[3]*y[3];
    #pragma unroll
    for (int off = 16; off; off >>= 1) {
        s  += __shfl_xor_sync(0xffffffffu, s,  off);
        s2 += __shfl_xor_sync(0xffffffffu, s2, off);
    }
    __shared__ float sh[8];
    int w = t >> 5;
    if ((t & 31) == 0) { sh[w] = s; sh[4 + w] = s2; }
    __syncthreads();
    float S  = sh[0]+sh[1]+sh[2]+sh[3];
    float S2 = sh[4]+sh[5]+sh[6]+sh[7];
    float mean = S * (1.0f/512.0f);
    float var  = S2 * (1.0f/512.0f) - mean * mean;
    float inv  = rsqrtf(var + 1e-6f);
    size_t base = (size_t)bp * DIM;   // packed at b*P1+p
    #pragma unroll
    for (int j = 0; j < 4; j++) {
        int c = t + j * 128;
        float v = (y[j] - mean) * inv * ln_g[c] + ln_b[c];
        __nv_bfloat16 hi = __float2bfloat16_rn(v);
        g_a1h[base + c] = hi;
        g_a1l[base + c] = __float2bfloat16_rn(v - __bfloat162float(hi));
    }
}

// ---------------- GRN sumsq: weighted column sums of h^2 ----------------
__global__ void sumsq_kernel() {
    int b = blockIdx.x;
    int ch = blockIdx.y * 128 + threadIdx.x;
    const float* hp = g_h + (size_t)(b * P1) * INTER + ch;
    float s = 0.f;
    #pragma unroll 4
    for (int p = 0; p < 515; p++) { float v = hp[(size_t)p * INTER]; s += v * v; }
    float v = hp[(size_t)515 * INTER];
    s += CONST_W * v * v;
    g_sumsq[b * INTER + ch] = s;
}

// ---------------- GRN finalize: alpha = grn_g * nx + 1 ----------------
__global__ void alpha_kernel(const float* __restrict__ grn_g) {
    int b = blockIdx.x;
    int i = threadIdx.x;
    float gx = sqrtf(g_sumsq[b * INTER + i]);
    float r = gx;
    #pragma unroll
    for (int off = 16; off; off >>= 1) r += __shfl_xor_sync(0xffffffffu, r, off);
    __shared__ float sh[32];
    __shared__ float meansh;
    if ((i & 31) == 0) sh[i >> 5] = r;
    __syncthreads();
    if (i < 32) {
        float v = sh[i];
        #pragma unroll
        for (int off = 16; off; off >>= 1) v += __shfl_xor_sync(0xffffffffu, v, off);
        if (i == 0) meansh = v * (1.0f/1024.0f);
    }
    __syncthreads();
    float nx = gx / (meansh + 1e-6f);
    g_alpha[b * INTER + i] = grn_g[i] * nx + 1.0f;
}

// ---------------- GRN transform: A2 = alpha*h + grn_b -> bf16 hi/lo ----------------
__global__ void transform_kernel(const float* __restrict__ grn_b) {
    int row = blockIdx.x;             // b*512 + p
    int b = row >> 9, p = row & 511;
    const float* h  = g_h + (size_t)(b * P1 + p) * INTER;
    const float* al = g_alpha + b * INTER;
    __nv_bfloat16* oh = g_a2h + (size_t)row * INTER;
    __nv_bfloat16* ol = g_a2l + (size_t)row * INTER;
    int i = threadIdx.x * 4;
    float4 hv = *(const float4*)&h[i];
    float4 av = *(const float4*)&al[i];
    float4 gb = *(const float4*)&grn_b[i];
    float v0 = av.x * hv.x + gb.x;
    float v1 = av.y * hv.y + gb.y;
    float v2 = av.z * hv.z + gb.z;
    float v3 = av.w * hv.w + gb.w;
    __nv_bfloat16 h0 = __float2bfloat16_rn(v0), h1 = __float2bfloat16_rn(v1);
    __nv_bfloat16 h2 = __float2bfloat16_rn(v2), h3 = __float2bfloat16_rn(v3);
    __nv_bfloat162 hp0(h0, h1), hp1(h2, h3);
    __nv_bfloat162 lp0(__float2bfloat16_rn(v0 - __bfloat162float(h0)),
                       __float2bfloat16_rn(v1 - __bfloat162float(h1)));
    __nv_bfloat162 lp1(__float2bfloat16_rn(v2 - __bfloat162float(h2)),
                       __float2bfloat16_rn(v3 - __bfloat162float(h3)));
    *(__nv_bfloat162*)&oh[i]     = hp0;
    *(__nv_bfloat162*)&oh[i + 2] = hp1;
    *(__nv_bfloat162*)&ol[i]     = lp0;
    *(__nv_bfloat162*)&ol[i + 2] = lp1;
}

// ---------------- weight transpose + hi/lo split ----------------
__global__ void prep_w(const float* __restrict__ pw1_w, const float* __restrict__ pw2_w) {
    int which = blockIdx.z & 1;
    int l = blockIdx.z >> 1;
    const float* src; __nv_bfloat16 *dh, *dl;
    int R, C;
    if (which == 0) { src = pw1_w + (size_t)l * DIM * INTER; R = DIM;  C = INTER;
                      dh = g_w1h + (size_t)l * INTER * DIM; dl = g_w1l + (size_t)l * INTER * DIM; }
    else            { src = pw2_w + (size_t)l * INTER * DIM; R = INTER; C = DIM;
                      dh = g_w2h + (size_t)l * DIM * INTER; dl = g_w2l + (size_t)l * DIM * INTER; }
    int cx = blockIdx.x * 32, ry = blockIdx.y * 32;
    if (cx >= C || ry >= R) return;
    __shared__ float tl[32][33];
    int tx = threadIdx.x, ty = threadIdx.y;
    #pragma unroll
    for (int i = 0; i < 4; i++)
        tl[ty * 4 + i][tx] = src[(size_t)(ry + ty * 4 + i) * C + cx + tx];
    __syncthreads();
    #pragma unroll
    for (int i = 0; i < 4; i++) {
        float w = tl[tx][ty * 4 + i];
        __nv_bfloat16 hi = __float2bfloat16_rn(w);
        size_t o = (size_t)(cx + ty * 4 + i) * R + ry + tx;
        dh[o] = hi;
        dl[o] = __float2bfloat16_rn(w - __bfloat162float(hi));
    }
}

// ---------------- upsample ----------------
__global__ void upsample_kernel(const int* __restrict__ seq_len, float* __restrict__ out) {
    int bp = blockIdx.x;
    int b = bp >> 12, p = bp & 4095;
    int al = seq_len[b];
    float4* orow = (float4*)(out + (size_t)bp * DIM);
    if (p >= al) {
        for (int c = threadIdx.x; c < DIM / 4; c += blockDim.x)
            orow[c] = make_float4(0.f, 0.f, 0.f, 0.f);
        return;
    }
    int base  = al >> 9;
    int rem   = al & 511;
    int split = (512 - rem) * base;
    int j = (p < split) ? (p / base) : ((512 - rem) + (p - split) / (base + 1));
    if (j > 511) j = 511;
    const float4* xrow = (const float4*)(g_x + (size_t)(b * SEQ + j) * DIM);
    for (int c = threadIdx.x; c < DIM / 4; c += blockDim.x) orow[c] = xrow[c];
}

// ---------------- launch ----------------
extern "C" void kernel_launch(void* const* d_in, const int* in_sizes, int n_in,
                              void* d_out, int out_size) {
    const int*   text    = (const int*)  d_in[0];
    const int*   seq_len = (const int*)  d_in[1];
    const float* emb     = (const float*)d_in[2];
    const float* dw_w    = (const float*)d_in[3];
    const float* dw_b    = (const float*)d_in[4];
    const float* ln_g    = (const float*)d_in[5];
    const float* ln_b    = (const float*)d_in[6];
    const float* pw1_w   = (const float*)d_in[7];
    const float* pw1_b   = (const float*)d_in[8];
    const float* grn_g   = (const float*)d_in[9];
    const float* grn_b   = (const float*)d_in[10];
    const float* pw2_w   = (const float*)d_in[11];
    const float* pw2_b   = (const float*)d_in[12];
    float* out = (float*)d_out;

    static const int SMEM_BYTES = NSTAGE * (int)STAGE_BYTES;  // 96 KB
    cudaFuncSetAttribute(gemm1_mma, cudaFuncAttributeMaxDynamicSharedMemorySize, SMEM_BYTES);
    cudaFuncSetAttribute(gemm2_mma, cudaFuncAttributeMaxDynamicSharedMemorySize, SMEM_BYTES);

    prep_w<<<dim3(32, 32, 2 * NLAYERS), dim3(32, 8)>>>(pw1_w, pw2_w);
    embed_kernel<<<NB * SEQ, 128>>>(text, emb);
    for (int l = 0; l < NLAYERS; l++) {
        convln_kernel<<<NB * P1, 128>>>(dw_w + l * 7 * DIM, dw_b + l * DIM,
                                        ln_g + l * DIM, ln_b + l * DIM);
        gemm1_mma<<<dim3(INTER / 128, M1T), 256, SMEM_BYTES>>>(l, pw1_b + l * INTER);
        sumsq_kernel<<<dim3(NB, INTER / 128), 128>>>();
        alpha_kernel<<<NB, 1024>>>(grn_g + l * INTER);
        transform_kernel<<<NB * SEQ, 256>>>(grn_b + l * INTER);
        gemm2_mma<<<dim3(DIM / 128, NB * SEQ / 128, 2), 256, SMEM_BYTES>>>(l, pw2_b + l * DIM);
    }
    upsample_kernel<<<NB * MAXSEQ, 128>>>(seq_len, out);
}

// round 7
// speedup vs baseline: 2.9650x; 1.3791x over previous
#include <cuda_runtime.h>
#include <cuda_bf16.h>
#include <math.h>
#include <stdint.h>

#define NB 8
#define SEQ 512
#define MAXSEQ 4096
#define DIM 512
#define INTER 1024
#define NLAYERS 4
#define P1 516
#define M1 (NB*P1)            // 4128 gemm1 rows (packed)
#define M1T 33                // ceil(4128/128)
#define CONST_W 3581.0f

// ---------------- scratch ----------------
__device__ float         g_x   [NB*SEQ*DIM];
__device__ __nv_bfloat16 g_a1h [(M1T*128)*DIM];       // rows >= 4128 stay zero
__device__ __nv_bfloat16 g_a1l [(M1T*128)*DIM];
__device__ float         g_h   [(M1T*128)*INTER];     // packed rows b*516+p
__device__ __nv_bfloat16 g_a2h [NB*SEQ*INTER];
__device__ __nv_bfloat16 g_a2l [NB*SEQ*INTER];
__device__ __nv_bfloat16 g_w1h [NLAYERS*INTER*DIM];
__device__ __nv_bfloat16 g_w1l [NLAYERS*INTER*DIM];
__device__ __nv_bfloat16 g_w2h [NLAYERS*DIM*INTER];
__device__ __nv_bfloat16 g_w2l [NLAYERS*DIM*INTER];
__device__ float         g_sumsq[NB*INTER];           // zero-init; alpha_kernel resets
__device__ float         g_alpha[NB*INTER];

// ---------------- helpers ----------------
__device__ __forceinline__ uint32_t smem_u32(const void* p) {
    uint32_t a;
    asm("{ .reg .u64 t; cvta.to.shared.u64 t, %1; cvt.u32.u64 %0, t; }" : "=r"(a) : "l"(p));
    return a;
}

#define STAGE_BYTES 32768u      // A 16KB + B 16KB
#define NSTAGE 3

// ---------------- compute one 64-K stage: warp tile 64x32 ----------------
__device__ __forceinline__ void compute_stage(uint32_t sbs,
                                              const uint32_t aoff[4], const uint32_t boff2[2],
                                              float acc[4][4][4]) {
    #pragma unroll
    for (int ks = 0; ks < 4; ks++) {
        uint32_t kx = (uint32_t)ks * 32u;
        uint32_t a_frag[4][4];
        #pragma unroll
        for (int i = 0; i < 4; i++)
            asm volatile("ldmatrix.sync.aligned.m8n8.x4.shared.b16 {%0,%1,%2,%3}, [%4];"
                : "=r"(a_frag[i][0]), "=r"(a_frag[i][1]), "=r"(a_frag[i][2]), "=r"(a_frag[i][3])
                : "r"((sbs + aoff[i]) ^ kx));
        uint32_t b_frag[4][2];
        #pragma unroll
        for (int jj = 0; jj < 2; jj++) {
            uint32_t r0, r1, r2, r3;
            asm volatile("ldmatrix.sync.aligned.m8n8.x4.shared.b16 {%0,%1,%2,%3}, [%4];"
                : "=r"(r0), "=r"(r1), "=r"(r2), "=r"(r3) : "r"((sbs + boff2[jj]) ^ kx));
            b_frag[jj*2+0][0] = r0; b_frag[jj*2+0][1] = r2;
            b_frag[jj*2+1][0] = r1; b_frag[jj*2+1][1] = r3;
        }
        #pragma unroll
        for (int i = 0; i < 4; i++)
            #pragma unroll
            for (int j = 0; j < 4; j++)
                asm volatile(
                    "mma.sync.aligned.m16n8k16.row.col.f32.bf16.bf16.f32 "
                    "{%0,%1,%2,%3}, {%4,%5,%6,%7}, {%8,%9}, {%0,%1,%2,%3};"
                    : "+f"(acc[i][j][0]), "+f"(acc[i][j][1]),
                      "+f"(acc[i][j][2]), "+f"(acc[i][j][3])
                    : "r"(a_frag[i][0]), "r"(a_frag[i][1]),
                      "r"(a_frag[i][2]), "r"(a_frag[i][3]),
                      "r"(b_frag[j][0]), "r"(b_frag[j][1]));
    }
}

// ---------------- mainloop over chunk range [c0, c1) ----------------
__device__ __forceinline__ void mma_mainloop(
    const __nv_bfloat16* a_hi, const __nv_bfloat16* a_lo,
    const __nv_bfloat16* b_hi, const __nv_bfloat16* b_lo,
    int K, int pc, int c0, int c1, int m0, int n0,
    uint32_t smem_base, int t, int warpM, int warpN, int lane,
    float acc[4][4][4]) {
    int lrow = t >> 3, lkg = t & 7;
    uint32_t so = (uint32_t)lrow * 128u + (((uint32_t)lkg * 16u) ^ (((uint32_t)lrow & 7u) * 16u));
    size_t srcoff = (size_t)lrow * K + lkg * 8;
    size_t rbytes = (size_t)32 * K * 2;

    const __nv_bfloat16* A0 = a_hi + (size_t)m0 * K + srcoff;
    const __nv_bfloat16* A1 = a_lo + (size_t)m0 * K + srcoff;
    const __nv_bfloat16* B0 = b_hi + (size_t)n0 * K + srcoff;
    const __nv_bfloat16* B2 = b_lo + (size_t)n0 * K + srcoff;

    int ph = c0 / pc;
    int kk = c0 - ph * pc;
    const __nv_bfloat16* pA = ((ph == 1) ? A1 : A0) + (size_t)kk * 64;
    const __nv_bfloat16* pB = B0 + (size_t)kk * 64;

    int la = lane & 15, lh = lane >> 4;
    uint32_t aoff[4], boff2[2];
    #pragma unroll
    for (int i = 0; i < 4; i++) {
        uint32_t row = (uint32_t)(warpM * 64 + i * 16 + la);
        aoff[i] = row * 128u + (((uint32_t)lh * 16u) ^ ((row & 7u) * 16u));
    }
    #pragma unroll
    for (int jj = 0; jj < 2; jj++) {
        uint32_t row = (uint32_t)(warpN * 32 + jj * 16 + la);
        boff2[jj] = 16384u + row * 128u + (((uint32_t)lh * 16u) ^ ((row & 7u) * 16u));
    }

#define ISSUE(slot) do { \
    uint32_t dst = smem_base + (uint32_t)(slot) * STAGE_BYTES; \
    const char* sa = (const char*)pA; const char* sb = (const char*)pB; \
    _Pragma("unroll") \
    for (int ii = 0; ii < 4; ii++) { \
        asm volatile("cp.async.cg.shared.global [%0], [%1], 16;" \
                     :: "r"(dst + so + (uint32_t)ii * 4096u), "l"(sa)); \
        asm volatile("cp.async.cg.shared.global [%0], [%1], 16;" \
                     :: "r"(dst + 16384u + so + (uint32_t)ii * 4096u), "l"(sb)); \
        sa += rbytes; sb += rbytes; } } while(0)

#define ADV() do { pA += 64; pB += 64; \
    if (++kk == pc) { kk = 0; ph++; \
        if (ph == 1) { pA = A1; pB = B0; } \
        else if (ph == 2) { pA = A0; pB = B2; } } } while(0)

    ISSUE(0); asm volatile("cp.async.commit_group;" ::: "memory"); ADV();
    ISSUE(1); asm volatile("cp.async.commit_group;" ::: "memory"); ADV();
    int stage = 0, pf_slot = 2;
    for (int kc = c0; kc < c1; kc++) {
        asm volatile("cp.async.wait_group 1;" ::: "memory");
        __syncthreads();
        if (kc + 2 < c1) {
            ISSUE(pf_slot); ADV();
            pf_slot = (pf_slot + 1 == NSTAGE) ? 0 : pf_slot + 1;
        }
        asm volatile("cp.async.commit_group;" ::: "memory");
        compute_stage(smem_base + (uint32_t)stage * STAGE_BYTES, aoff, boff2, acc);
        stage = (stage + 1 == NSTAGE) ? 0 : stage + 1;
    }
#undef ISSUE
#undef ADV
}

__device__ __forceinline__ float gelu_exact(float v) {
    return 0.5f * v * (1.0f + erff(v * 0.7071067811865476f));
}

// ---------------- GEMM1: h = gelu(A1 @ W1t^T + b), fused GRN sumsq ----------------
__global__ void __launch_bounds__(256, 2) gemm1_mma(int l, const float* __restrict__ bias) {
    extern __shared__ char smem[];
    uint32_t sbase = smem_u32(smem);
    int t = threadIdx.x, lane = t & 31, wid = t >> 5;
    int warpM = wid & 1, warpN = wid >> 1;           // 2M x 4N warps (64x32 tiles)
    int n0 = blockIdx.x * 128, m0 = blockIdx.y * 128;
    float acc[4][4][4] = {};
    mma_mainloop(g_a1h, g_a1l,
                 g_w1h + (size_t)l * INTER * DIM, g_w1l + (size_t)l * INTER * DIM,
                 DIM, 8, 0, 24, m0, n0, sbase, t, warpM, warpN, lane, acc);
    int b_lo = m0 / P1;
    int boundary = (b_lo + 1) * P1;
    float cs[2][4][2] = {};
    #pragma unroll
    for (int i = 0; i < 4; i++) {
        #pragma unroll
        for (int half = 0; half < 2; half++) {
            int r = m0 + warpM * 64 + i * 16 + (lane >> 2) + 8 * half;
            int bs = (r >= boundary) ? 1 : 0;
            int p = r - (bs ? boundary : b_lo * P1);
            float wgt = (r >= M1) ? 0.0f :
                        ((p < 515) ? 1.0f : ((p == 515) ? CONST_W : 0.0f));
            #pragma unroll
            for (int j = 0; j < 4; j++) {
                int n = n0 + warpN * 32 + j * 8 + (lane & 3) * 2;
                float g0 = gelu_exact(acc[i][j][half*2+0] + bias[n]);
                float g1 = gelu_exact(acc[i][j][half*2+1] + bias[n+1]);
                cs[bs][j][0] += wgt * g0 * g0;
                cs[bs][j][1] += wgt * g1 * g1;
                if (r < M1)
                    *(float2*)&g_h[(size_t)r * INTER + n] = make_float2(g0, g1);
            }
        }
    }
    // reduce both buckets over the 8 lanes sharing the same columns
    #pragma unroll
    for (int bs = 0; bs < 2; bs++)
        #pragma unroll
        for (int j = 0; j < 4; j++)
            #pragma unroll
            for (int s = 0; s < 2; s++) {
                float v = cs[bs][j][s];
                v += __shfl_xor_sync(0xffffffffu, v, 4);
                v += __shfl_xor_sync(0xffffffffu, v, 8);
                v += __shfl_xor_sync(0xffffffffu, v, 16);
                cs[bs][j][s] = v;
            }
    if (lane < 4) {
        #pragma unroll
        for (int j = 0; j < 4; j++) {
            int n = n0 + warpN * 32 + j * 8 + lane * 2;
            atomicAdd(&g_sumsq[b_lo * INTER + n],     cs[0][j][0]);
            atomicAdd(&g_sumsq[b_lo * INTER + n + 1], cs[0][j][1]);
            if (b_lo + 1 < NB) {
                atomicAdd(&g_sumsq[(b_lo + 1) * INTER + n],     cs[1][j][0]);
                atomicAdd(&g_sumsq[(b_lo + 1) * INTER + n + 1], cs[1][j][1]);
            }
        }
    }
}

// ---------------- GEMM2: x += A2 @ W2t^T + b  (K-split 2, atomic epilogue) ----------------
__global__ void __launch_bounds__(256, 2) gemm2_mma(int l, const float* __restrict__ bias) {
    extern __shared__ char smem[];
    uint32_t sbase = smem_u32(smem);
    int t = threadIdx.x, lane = t & 31, wid = t >> 5;
    int warpM = wid & 1, warpN = wid >> 1;
    int n0 = blockIdx.x * 128, m0 = blockIdx.y * 128;
    int split = blockIdx.z;
    float acc[4][4][4] = {};
    mma_mainloop(g_a2h, g_a2l,
                 g_w2h + (size_t)l * DIM * INTER, g_w2l + (size_t)l * DIM * INTER,
                 INTER, 16, split * 24, split * 24 + 24, m0, n0,
                 sbase, t, warpM, warpN, lane, acc);
    #pragma unroll
    for (int i = 0; i < 4; i++) {
        int rowbase = m0 + warpM * 64 + i * 16 + (lane >> 2);
        #pragma unroll
        for (int half = 0; half < 2; half++) {
            int m = rowbase + 8 * half;
            #pragma unroll
            for (int j = 0; j < 4; j++) {
                int n = n0 + warpN * 32 + j * 8 + (lane & 3) * 2;
                size_t xo = (size_t)m * DIM + n;
                float add0 = acc[i][j][half*2+0];
                float add1 = acc[i][j][half*2+1];
                if (split == 0) { add0 += bias[n]; add1 += bias[n+1]; }
                atomicAdd(&g_x[xo],     add0);
                atomicAdd(&g_x[xo + 1], add1);
            }
        }
    }
}

// ---------------- embed + abs pos enc (paired sincos) ----------------
__global__ void embed_kernel(const int* __restrict__ text, const float* __restrict__ emb) {
    int bp = blockIdx.x;
    int p = bp & 511, b = bp >> 9;
    int tok = text[b * SEQ + p] + 1;
    const float* erow = emb + (size_t)tok * DIM;
    float* orow = g_x + (size_t)bp * DIM;
    int i = threadIdx.x;               // 256 threads, pair (i, i+256)
    float f   = expf(-9.210340371976184f * (float)i / 256.0f);
    float ang = (float)p * f;
    float sv, cv;
    sincosf(ang, &sv, &cv);
    orow[i]       = erow[i]       + cv;
    orow[i + 256] = erow[i + 256] + sv;
}

// ---------------- dwconv(k=7) + LayerNorm -> bf16 hi/lo (packed rows) ----------------
__global__ void convln_kernel(const float* __restrict__ dw_w, const float* __restrict__ dw_b,
                              const float* __restrict__ ln_g, const float* __restrict__ ln_b) {
    int bp = blockIdx.x;              // b*P1 + p
    int b = bp / P1;
    int p = bp - b * P1;
    int t = threadIdx.x;
    float y[4];
    #pragma unroll
    for (int j = 0; j < 4; j++) {
        int c = t + j * 128;
        float acc = dw_b[c];
        #pragma unroll
        for (int k = 0; k < 7; k++) {
            int pp = p - 3 + k;
            if (pp >= 0 && pp < SEQ)
                acc += dw_w[k * DIM + c] * g_x[(size_t)(b * SEQ + pp) * DIM + c];
        }
        y[j] = acc;
    }
    float s = y[0]+y[1]+y[2]+y[3];
    float s2 = y[0]*y[0]+y[1]*y[1]+y[2]*y[2]+y[3]*y[3];
    #pragma unroll
    for (int off = 16; off; off >>= 1) {
        s  += __shfl_xor_sync(0xffffffffu, s,  off);
        s2 += __shfl_xor_sync(0xffffffffu, s2, off);
    }
    __shared__ float sh[8];
    int w = t >> 5;
    if ((t & 31) == 0) { sh[w] = s; sh[4 + w] = s2; }
    __syncthreads();
    float S  = sh[0]+sh[1]+sh[2]+sh[3];
    float S2 = sh[4]+sh[5]+sh[6]+sh[7];
    float mean = S * (1.0f/512.0f);
    float var  = S2 * (1.0f/512.0f) - mean * mean;
    float inv  = rsqrtf(var + 1e-6f);
    size_t base = (size_t)bp * DIM;
    #pragma unroll
    for (int j = 0; j < 4; j++) {
        int c = t + j * 128;
        float v = (y[j] - mean) * inv * ln_g[c] + ln_b[c];
        __nv_bfloat16 hi = __float2bfloat16_rn(v);
        g_a1h[base + c] = hi;
        g_a1l[base + c] = __float2bfloat16_rn(v - __bfloat162float(hi));
    }
}

// ---------------- GRN finalize: alpha = grn_g * nx + 1; resets sumsq ----------------
__global__ void alpha_kernel(const float* __restrict__ grn_g) {
    int b = blockIdx.x;
    int i = threadIdx.x;
    float gx = sqrtf(g_sumsq[b * INTER + i]);
    g_sumsq[b * INTER + i] = 0.0f;    // reset for next layer / next replay
    float r = gx;
    #pragma unroll
    for (int off = 16; off; off >>= 1) r += __shfl_xor_sync(0xffffffffu, r, off);
    __shared__ float sh[32];
    __shared__ float meansh;
    if ((i & 31) == 0) sh[i >> 5] = r;
    __syncthreads();
    if (i < 32) {
        float v = sh[i];
        #pragma unroll
        for (int off = 16; off; off >>= 1) v += __shfl_xor_sync(0xffffffffu, v, off);
        if (i == 0) meansh = v * (1.0f/1024.0f);
    }
    __syncthreads();
    float nx = gx / (meansh + 1e-6f);
    g_alpha[b * INTER + i] = grn_g[i] * nx + 1.0f;
}

// ---------------- GRN transform: A2 = alpha*h + grn_b -> bf16 hi/lo ----------------
__global__ void transform_kernel(const float* __restrict__ grn_b) {
    int row = blockIdx.x;             // b*512 + p
    int b = row >> 9, p = row & 511;
    const float* h  = g_h + (size_t)(b * P1 + p) * INTER;
    const float* al = g_alpha + b * INTER;
    __nv_bfloat16* oh = g_a2h + (size_t)row * INTER;
    __nv_bfloat16* ol = g_a2l + (size_t)row * INTER;
    int i = threadIdx.x * 4;
    float4 hv = *(const float4*)&h[i];
    float4 av = *(const float4*)&al[i];
    float4 gb = *(const float4*)&grn_b[i];
    float v0 = av.x * hv.x + gb.x;
    float v1 = av.y * hv.y + gb.y;
    float v2 = av.z * hv.z + gb.z;
    float v3 = av.w * hv.w + gb.w;
    __nv_bfloat16 h0 = __float2bfloat16_rn(v0), h1 = __float2bfloat16_rn(v1);
    __nv_bfloat16 h2 = __float2bfloat16_rn(v2), h3 = __float2bfloat16_rn(v3);
    __nv_bfloat162 hp0(h0, h1), hp1(h2, h3);
    __nv_bfloat162 lp0(__float2bfloat16_rn(v0 - __bfloat162float(h0)),
                       __float2bfloat16_rn(v1 - __bfloat162float(h1)));
    __nv_bfloat162 lp1(__float2bfloat16_rn(v2 - __bfloat162float(h2)),
                       __float2bfloat16_rn(v3 - __bfloat162float(h3)));
    *(__nv_bfloat162*)&oh[i]     = hp0;
    *(__nv_bfloat162*)&oh[i + 2] = hp1;
    *(__nv_bfloat162*)&ol[i]     = lp0;
    *(__nv_bfloat162*)&ol[i + 2] = lp1;
}

// ---------------- weight transpose + hi/lo split ----------------
__global__ void prep_w(const float* __restrict__ pw1_w, const float* __restrict__ pw2_w) {
    int which = blockIdx.z & 1;
    int l = blockIdx.z >> 1;
    const float* src; __nv_bfloat16 *dh, *dl;
    int R, C;
    if (which == 0) { src = pw1_w + (size_t)l * DIM * INTER; R = DIM;  C = INTER;
                      dh = g_w1h + (size_t)l * INTER * DIM; dl = g_w1l + (size_t)l * INTER * DIM; }
    else            { src = pw2_w + (size_t)l * INTER * DIM; R = INTER; C = DIM;
                      dh = g_w2h + (size_t)l * DIM * INTER; dl = g_w2l + (size_t)l * DIM * INTER; }
    int cx = blockIdx.x * 32, ry = blockIdx.y * 32;
    if (cx >= C || ry >= R) return;
    __shared__ float tl[32][33];
    int tx = threadIdx.x, ty = threadIdx.y;
    #pragma unroll
    for (int i = 0; i < 4; i++)
        tl[ty * 4 + i][tx] = src[(size_t)(ry + ty * 4 + i) * C + cx + tx];
    __syncthreads();
    #pragma unroll
    for (int i = 0; i < 4; i++) {
        float w = tl[tx][ty * 4 + i];
        __nv_bfloat16 hi = __float2bfloat16_rn(w);
        size_t o = (size_t)(cx + ty * 4 + i) * R + ry + tx;
        dh[o] = hi;
        dl[o] = __float2bfloat16_rn(w - __bfloat162float(hi));
    }
}

// ---------------- upsample ----------------
__global__ void upsample_kernel(const int* __restrict__ seq_len, float* __restrict__ out) {
    int bp = blockIdx.x;
    int b = bp >> 12, p = bp & 4095;
    int al = seq_len[b];
    float4* orow = (float4*)(out + (size_t)bp * DIM);
    if (p >= al) {
        for (int c = threadIdx.x; c < DIM / 4; c += blockDim.x)
            orow[c] = make_float4(0.f, 0.f, 0.f, 0.f);
        return;
    }
    int base  = al >> 9;
    int rem   = al & 511;
    int split = (512 - rem) * base;
    int j = (p < split) ? (p / base) : ((512 - rem) + (p - split) / (base + 1));
    if (j > 511) j = 511;
    const float4* xrow = (const float4*)(g_x + (size_t)(b * SEQ + j) * DIM);
    for (int c = threadIdx.x; c < DIM / 4; c += blockDim.x) orow[c] = xrow[c];
}

// ---------------- launch ----------------
extern "C" void kernel_launch(void* const* d_in, const int* in_sizes, int n_in,
                              void* d_out, int out_size) {
    const int*   text    = (const int*)  d_in[0];
    const int*   seq_len = (const int*)  d_in[1];
    const float* emb     = (const float*)d_in[2];
    const float* dw_w    = (const float*)d_in[3];
    const float* dw_b    = (const float*)d_in[4];
    const float* ln_g    = (const float*)d_in[5];
    const float* ln_b    = (const float*)d_in[6];
    const float* pw1_w   = (const float*)d_in[7];
    const float* pw1_b   = (const float*)d_in[8];
    const float* grn_g   = (const float*)d_in[9];
    const float* grn_b   = (const float*)d_in[10];
    const float* pw2_w   = (const float*)d_in[11];
    const float* pw2_b   = (const float*)d_in[12];
    float* out = (float*)d_out;

    static const int SMEM_BYTES = NSTAGE * (int)STAGE_BYTES;  // 96 KB
    cudaFuncSetAttribute(gemm1_mma, cudaFuncAttributeMaxDynamicSharedMemorySize, SMEM_BYTES);
    cudaFuncSetAttribute(gemm2_mma, cudaFuncAttributeMaxDynamicSharedMemorySize, SMEM_BYTES);

    prep_w<<<dim3(32, 32, 2 * NLAYERS), dim3(32, 8)>>>(pw1_w, pw2_w);
    embed_kernel<<<NB * SEQ, 256>>>(text, emb);
    for (int l = 0; l < NLAYERS; l++) {
        convln_kernel<<<NB * P1, 128>>>(dw_w + l * 7 * DIM, dw_b + l * DIM,
                                        ln_g + l * DIM, ln_b + l * DIM);
        gemm1_mma<<<dim3(INTER / 128, M1T), 256, SMEM_BYTES>>>(l, pw1_b + l * INTER);
        alpha_kernel<<<NB, 1024>>>(grn_g + l * INTER);
        transform_kernel<<<NB * SEQ, 256>>>(grn_b + l * INTER);
        gemm2_mma<<<dim3(DIM / 128, NB * SEQ / 128, 2), 256, SMEM_BYTES>>>(l, pw2_b + l * DIM);
    }
    upsample_kernel<<<NB * MAXSEQ, 128>>>(seq_len, out);
}

// round 8
// speedup vs baseline: 2.9793x; 1.0048x over previous
#include <cuda_runtime.h>
#include <cuda_bf16.h>
#include <math.h>
#include <stdint.h>

#define NB 8
#define SEQ 512
#define MAXSEQ 4096
#define DIM 512
#define INTER 1024
#define NLAYERS 4
#define P1 516
#define M1 (NB*P1)            // 4128 gemm1 rows (packed)
#define M1T 33                // ceil(4128/128)
#define CONST_W 3581.0f

// ---------------- scratch ----------------
__device__ float         g_x   [NB*SEQ*DIM];
__device__ __nv_bfloat16 g_a1h [(M1T*128)*DIM];
__device__ __nv_bfloat16 g_a1l [(M1T*128)*DIM];
__device__ float         g_h   [(M1T*128)*INTER];
__device__ __nv_bfloat16 g_a2h [NB*SEQ*INTER];
__device__ __nv_bfloat16 g_a2l [NB*SEQ*INTER];
__device__ __nv_bfloat16 g_w1h [NLAYERS*INTER*DIM];
__device__ __nv_bfloat16 g_w1l [NLAYERS*INTER*DIM];
__device__ __nv_bfloat16 g_w2h [NLAYERS*DIM*INTER];
__device__ __nv_bfloat16 g_w2l [NLAYERS*DIM*INTER];
__device__ float         g_sumsq[NB*INTER];
__device__ float         g_alpha[NB*INTER];

// ---------------- helpers ----------------
__device__ __forceinline__ uint32_t smem_u32(const void* p) {
    uint32_t a;
    asm("{ .reg .u64 t; cvta.to.shared.u64 t, %1; cvt.u32.u64 %0, t; }" : "=r"(a) : "l"(p));
    return a;
}

#define STAGE_BYTES 32768u      // A 16KB + B 16KB
#define NSTAGE 3

// ---------------- compute one 64-K stage: warp tile 64x64 (4 warps, 2x2) ----------------
__device__ __forceinline__ void compute_stage(uint32_t sbs,
                                              const uint32_t aoff[4], const uint32_t boff[4],
                                              float acc[4][8][4]) {
    #pragma unroll
    for (int ks = 0; ks < 4; ks++) {
        uint32_t kx = (uint32_t)ks * 32u;
        uint32_t a_frag[4][4];
        #pragma unroll
        for (int i = 0; i < 4; i++)
            asm volatile("ldmatrix.sync.aligned.m8n8.x4.shared.b16 {%0,%1,%2,%3}, [%4];"
                : "=r"(a_frag[i][0]), "=r"(a_frag[i][1]), "=r"(a_frag[i][2]), "=r"(a_frag[i][3])
                : "r"((sbs + aoff[i]) ^ kx));
        uint32_t b_frag[8][2];
        #pragma unroll
        for (int jj = 0; jj < 4; jj++) {
            uint32_t r0, r1, r2, r3;
            asm volatile("ldmatrix.sync.aligned.m8n8.x4.shared.b16 {%0,%1,%2,%3}, [%4];"
                : "=r"(r0), "=r"(r1), "=r"(r2), "=r"(r3) : "r"((sbs + boff[jj]) ^ kx));
            b_frag[jj*2+0][0] = r0; b_frag[jj*2+0][1] = r2;
            b_frag[jj*2+1][0] = r1; b_frag[jj*2+1][1] = r3;
        }
        #pragma unroll
        for (int i = 0; i < 4; i++)
            #pragma unroll
            for (int j = 0; j < 8; j++)
                asm volatile(
                    "mma.sync.aligned.m16n8k16.row.col.f32.bf16.bf16.f32 "
                    "{%0,%1,%2,%3}, {%4,%5,%6,%7}, {%8,%9}, {%0,%1,%2,%3};"
                    : "+f"(acc[i][j][0]), "+f"(acc[i][j][1]),
                      "+f"(acc[i][j][2]), "+f"(acc[i][j][3])
                    : "r"(a_frag[i][0]), "r"(a_frag[i][1]),
                      "r"(a_frag[i][2]), "r"(a_frag[i][3]),
                      "r"(b_frag[j][0]), "r"(b_frag[j][1]));
    }
}

// ---------------- mainloop over chunk range [c0, c1) ----------------
__device__ __forceinline__ void mma_mainloop(
    const __nv_bfloat16* a_hi, const __nv_bfloat16* a_lo,
    const __nv_bfloat16* b_hi, const __nv_bfloat16* b_lo,
    int K, int pc, int c0, int c1, int m0, int n0,
    uint32_t smem_base, int t, int warpM, int warpN, int lane,
    float acc[4][8][4]) {
    // 128 threads: 16 rows x 8 16B-groups per iteration, 8 iterations each for A/B
    int lrow = t >> 3, lkg = t & 7;
    uint32_t so = (uint32_t)lrow * 128u + (((uint32_t)lkg * 16u) ^ (((uint32_t)lrow & 7u) * 16u));
    size_t srcoff = (size_t)lrow * K + lkg * 8;
    size_t rbytes = (size_t)16 * K * 2;           // 16 rows, bytes

    const __nv_bfloat16* A0 = a_hi + (size_t)m0 * K + srcoff;
    const __nv_bfloat16* A1 = a_lo + (size_t)m0 * K + srcoff;
    const __nv_bfloat16* B0 = b_hi + (size_t)n0 * K + srcoff;
    const __nv_bfloat16* B2 = b_lo + (size_t)n0 * K + srcoff;

    int ph = c0 / pc;
    int kk = c0 - ph * pc;
    const __nv_bfloat16* pA = ((ph == 1) ? A1 : A0) + (size_t)kk * 64;
    const __nv_bfloat16* pB = B0 + (size_t)kk * 64;

    int la = lane & 15, lh = lane >> 4;
    uint32_t aoff[4], boff[4];
    #pragma unroll
    for (int i = 0; i < 4; i++) {
        uint32_t row = (uint32_t)(warpM * 64 + i * 16 + la);
        aoff[i] = row * 128u + (((uint32_t)lh * 16u) ^ ((row & 7u) * 16u));
    }
    #pragma unroll
    for (int jj = 0; jj < 4; jj++) {
        uint32_t row = (uint32_t)(warpN * 64 + jj * 16 + la);
        boff[jj] = 16384u + row * 128u + (((uint32_t)lh * 16u) ^ ((row & 7u) * 16u));
    }

#define ISSUE(slot) do { \
    uint32_t dst = smem_base + (uint32_t)(slot) * STAGE_BYTES; \
    const char* sa = (const char*)pA; const char* sb = (const char*)pB; \
    _Pragma("unroll") \
    for (int ii = 0; ii < 8; ii++) { \
        asm volatile("cp.async.cg.shared.global [%0], [%1], 16;" \
                     :: "r"(dst + so + (uint32_t)ii * 2048u), "l"(sa)); \
        asm volatile("cp.async.cg.shared.global [%0], [%1], 16;" \
                     :: "r"(dst + 16384u + so + (uint32_t)ii * 2048u), "l"(sb)); \
        sa += rbytes; sb += rbytes; } } while(0)

#define ADV() do { pA += 64; pB += 64; \
    if (++kk == pc) { kk = 0; ph++; \
        if (ph == 1) { pA = A1; pB = B0; } \
        else if (ph == 2) { pA = A0; pB = B2; } } } while(0)

    ISSUE(0); asm volatile("cp.async.commit_group;" ::: "memory"); ADV();
    ISSUE(1); asm volatile("cp.async.commit_group;" ::: "memory"); ADV();
    int stage = 0, pf_slot = 2;
    for (int kc = c0; kc < c1; kc++) {
        asm volatile("cp.async.wait_group 1;" ::: "memory");
        __syncthreads();
        if (kc + 2 < c1) {
            ISSUE(pf_slot); ADV();
            pf_slot = (pf_slot + 1 == NSTAGE) ? 0 : pf_slot + 1;
        }
        asm volatile("cp.async.commit_group;" ::: "memory");
        compute_stage(smem_base + (uint32_t)stage * STAGE_BYTES, aoff, boff, acc);
        stage = (stage + 1 == NSTAGE) ? 0 : stage + 1;
    }
#undef ISSUE
#undef ADV
}

__device__ __forceinline__ float gelu_exact(float v) {
    return 0.5f * v * (1.0f + erff(v * 0.7071067811865476f));
}

// ---------------- GEMM1: h = gelu(A1 @ W1t^T + b), fused GRN sumsq ----------------
__global__ void __launch_bounds__(128, 2) gemm1_mma(int l, const float* __restrict__ bias) {
    extern __shared__ char smem[];
    uint32_t sbase = smem_u32(smem);
    int t = threadIdx.x, lane = t & 31, wid = t >> 5;
    int warpM = wid & 1, warpN = wid >> 1;           // 2x2 warps, 64x64 tiles
    int n0 = blockIdx.x * 128, m0 = blockIdx.y * 128;
    float acc[4][8][4] = {};
    mma_mainloop(g_a1h, g_a1l,
                 g_w1h + (size_t)l * INTER * DIM, g_w1l + (size_t)l * INTER * DIM,
                 DIM, 8, 0, 24, m0, n0, sbase, t, warpM, warpN, lane, acc);
    int b_lo = m0 / P1;
    int boundary = (b_lo + 1) * P1;
    float cs[2][8][2] = {};
    #pragma unroll
    for (int i = 0; i < 4; i++) {
        #pragma unroll
        for (int half = 0; half < 2; half++) {
            int r = m0 + warpM * 64 + i * 16 + (lane >> 2) + 8 * half;
            int bs = (r >= boundary) ? 1 : 0;
            int p = r - (bs ? boundary : b_lo * P1);
            float wgt = (r >= M1) ? 0.0f :
                        ((p < 515) ? 1.0f : ((p == 515) ? CONST_W : 0.0f));
            #pragma unroll
            for (int j = 0; j < 8; j++) {
                int n = n0 + warpN * 64 + j * 8 + (lane & 3) * 2;
                float g0 = gelu_exact(acc[i][j][half*2+0] + bias[n]);
                float g1 = gelu_exact(acc[i][j][half*2+1] + bias[n+1]);
                cs[bs][j][0] += wgt * g0 * g0;
                cs[bs][j][1] += wgt * g1 * g1;
                if (r < M1)
                    *(float2*)&g_h[(size_t)r * INTER + n] = make_float2(g0, g1);
            }
        }
    }
    #pragma unroll
    for (int bs = 0; bs < 2; bs++)
        #pragma unroll
        for (int j = 0; j < 8; j++)
            #pragma unroll
            for (int s = 0; s < 2; s++) {
                float v = cs[bs][j][s];
                v += __shfl_xor_sync(0xffffffffu, v, 4);
                v += __shfl_xor_sync(0xffffffffu, v, 8);
                v += __shfl_xor_sync(0xffffffffu, v, 16);
                cs[bs][j][s] = v;
            }
    if (lane < 4) {
        #pragma unroll
        for (int j = 0; j < 8; j++) {
            int n = n0 + warpN * 64 + j * 8 + lane * 2;
            atomicAdd(&g_sumsq[b_lo * INTER + n],     cs[0][j][0]);
            atomicAdd(&g_sumsq[b_lo * INTER + n + 1], cs[0][j][1]);
            if (b_lo + 1 < NB) {
                atomicAdd(&g_sumsq[(b_lo + 1) * INTER + n],     cs[1][j][0]);
                atomicAdd(&g_sumsq[(b_lo + 1) * INTER + n + 1], cs[1][j][1]);
            }
        }
    }
}

// ---------------- GEMM2: x += A2 @ W2t^T + b  (K-split 2, atomic epilogue) ----------------
__global__ void __launch_bounds__(128, 2) gemm2_mma(int l, const float* __restrict__ bias) {
    extern __shared__ char smem[];
    uint32_t sbase = smem_u32(smem);
    int t = threadIdx.x, lane = t & 31, wid = t >> 5;
    int warpM = wid & 1, warpN = wid >> 1;
    int n0 = blockIdx.x * 128, m0 = blockIdx.y * 128;
    int split = blockIdx.z;
    float acc[4][8][4] = {};
    mma_mainloop(g_a2h, g_a2l,
                 g_w2h + (size_t)l * DIM * INTER, g_w2l + (size_t)l * DIM * INTER,
                 INTER, 16, split * 24, split * 24 + 24, m0, n0,
                 sbase, t, warpM, warpN, lane, acc);
    #pragma unroll
    for (int i = 0; i < 4; i++) {
        int rowbase = m0 + warpM * 64 + i * 16 + (lane >> 2);
        #pragma unroll
        for (int half = 0; half < 2; half++) {
            int m = rowbase + 8 * half;
            #pragma unroll
            for (int j = 0; j < 8; j++) {
                int n = n0 + warpN * 64 + j * 8 + (lane & 3) * 2;
                size_t xo = (size_t)m * DIM + n;
                float add0 = acc[i][j][half*2+0];
                float add1 = acc[i][j][half*2+1];
                if (split == 0) { add0 += bias[n]; add1 += bias[n+1]; }
                atomicAdd(&g_x[xo],     add0);
                atomicAdd(&g_x[xo + 1], add1);
            }
        }
    }
}

// ---------------- embed + abs pos enc (paired sincos) ----------------
__global__ void embed_kernel(const int* __restrict__ text, const float* __restrict__ emb) {
    int bp = blockIdx.x;
    int p = bp & 511, b = bp >> 9;
    int tok = text[b * SEQ + p] + 1;
    const float* erow = emb + (size_t)tok * DIM;
    float* orow = g_x + (size_t)bp * DIM;
    int i = threadIdx.x;
    float f   = expf(-9.210340371976184f * (float)i / 256.0f);
    float ang = (float)p * f;
    float sv, cv;
    sincosf(ang, &sv, &cv);
    orow[i]       = erow[i]       + cv;
    orow[i + 256] = erow[i + 256] + sv;
}

// ---------------- dwconv(k=7) + LayerNorm -> bf16 hi/lo (packed rows) ----------------
__global__ void convln_kernel(const float* __restrict__ dw_w, const float* __restrict__ dw_b,
                              const float* __restrict__ ln_g, const float* __restrict__ ln_b) {
    int bp = blockIdx.x;
    int b = bp / P1;
    int p = bp - b * P1;
    int t = threadIdx.x;
    float y[4];
    #pragma unroll
    for (int j = 0; j < 4; j++) {
        int c = t + j * 128;
        float acc = dw_b[c];
        #pragma unroll
        for (int k = 0; k < 7; k++) {
            int pp = p - 3 + k;
            if (pp >= 0 && pp < SEQ)
                acc += dw_w[k * DIM + c] * g_x[(size_t)(b * SEQ + pp) * DIM + c];
        }
        y[j] = acc;
    }
    float s = y[0]+y[1]+y[2]+y[3];
    float s2 = y[0]*y[0]+y[1]*y[1]+y[2]*y[2]+y[3]*y[3];
    #pragma unroll
    for (int off = 16; off; off >>= 1) {
        s  += __shfl_xor_sync(0xffffffffu, s,  off);
        s2 += __shfl_xor_sync(0xffffffffu, s2, off);
    }
    __shared__ float sh[8];
    int w = t >> 5;
    if ((t & 31) == 0) { sh[w] = s; sh[4 + w] = s2; }
    __syncthreads();
    float S  = sh[0]+sh[1]+sh[2]+sh[3];
    float S2 = sh[4]+sh[5]+sh[6]+sh[7];
    float mean = S * (1.0f/512.0f);
    float var  = S2 * (1.0f/512.0f) - mean * mean;
    float inv  = rsqrtf(var + 1e-6f);
    size_t base = (size_t)bp * DIM;
    #pragma unroll
    for (int j = 0; j < 4; j++) {
        int c = t + j * 128;
        float v = (y[j] - mean) * inv * ln_g[c] + ln_b[c];
        __nv_bfloat16 hi = __float2bfloat16_rn(v);
        g_a1h[base + c] = hi;
        g_a1l[base + c] = __float2bfloat16_rn(v - __bfloat162float(hi));
    }
}

// ---------------- GRN finalize: alpha = grn_g * nx + 1; resets sumsq ----------------
__global__ void alpha_kernel(const float* __restrict__ grn_g) {
    int b = blockIdx.x;
    int i = threadIdx.x;
    float gx = sqrtf(g_sumsq[b * INTER + i]);
    g_sumsq[b * INTER + i] = 0.0f;
    float r = gx;
    #pragma unroll
    for (int off = 16; off; off >>= 1) r += __shfl_xor_sync(0xffffffffu, r, off);
    __shared__ float sh[32];
    __shared__ float meansh;
    if ((i & 31) == 0) sh[i >> 5] = r;
    __syncthreads();
    if (i < 32) {
        float v = sh[i];
        #pragma unroll
        for (int off = 16; off; off >>= 1) v += __shfl_xor_sync(0xffffffffu, v, off);
        if (i == 0) meansh = v * (1.0f/1024.0f);
    }
    __syncthreads();
    float nx = gx / (meansh + 1e-6f);
    g_alpha[b * INTER + i] = grn_g[i] * nx + 1.0f;
}

// ---------------- GRN transform: A2 = alpha*h + grn_b -> bf16 hi/lo ----------------
__global__ void transform_kernel(const float* __restrict__ grn_b) {
    int row = blockIdx.x;
    int b = row >> 9, p = row & 511;
    const float* h  = g_h + (size_t)(b * P1 + p) * INTER;
    const float* al = g_alpha + b * INTER;
    __nv_bfloat16* oh = g_a2h + (size_t)row * INTER;
    __nv_bfloat16* ol = g_a2l + (size_t)row * INTER;
    int i = threadIdx.x * 4;
    float4 hv = *(const float4*)&h[i];
    float4 av = *(const float4*)&al[i];
    float4 gb = *(const float4*)&grn_b[i];
    float v0 = av.x * hv.x + gb.x;
    float v1 = av.y * hv.y + gb.y;
    float v2 = av.z * hv.z + gb.z;
    float v3 = av.w * hv.w + gb.w;
    __nv_bfloat16 h0 = __float2bfloat16_rn(v0), h1 = __float2bfloat16_rn(v1);
    __nv_bfloat16 h2 = __float2bfloat16_rn(v2), h3 = __float2bfloat16_rn(v3);
    __nv_bfloat162 hp0(h0, h1), hp1(h2, h3);
    __nv_bfloat162 lp0(__float2bfloat16_rn(v0 - __bfloat162float(h0)),
                       __float2bfloat16_rn(v1 - __bfloat162float(h1)));
    __nv_bfloat162 lp1(__float2bfloat16_rn(v2 - __bfloat162float(h2)),
                       __float2bfloat16_rn(v3 - __bfloat162float(h3)));
    *(__nv_bfloat162*)&oh[i]     = hp0;
    *(__nv_bfloat162*)&oh[i + 2] = hp1;
    *(__nv_bfloat162*)&ol[i]     = lp0;
    *(__nv_bfloat162*)&ol[i + 2] = lp1;
}

// ---------------- weight transpose + hi/lo split ----------------
__global__ void prep_w(const float* __restrict__ pw1_w, const float* __restrict__ pw2_w) {
    int which = blockIdx.z & 1;
    int l = blockIdx.z >> 1;
    const float* src; __nv_bfloat16 *dh, *dl;
    int R, C;
    if (which == 0) { src = pw1_w + (size_t)l * DIM * INTER; R = DIM;  C = INTER;
                      dh = g_w1h + (size_t)l * INTER * DIM; dl = g_w1l + (size_t)l * INTER * DIM; }
    else            { src = pw2_w + (size_t)l * INTER * DIM; R = INTER; C = DIM;
                      dh = g_w2h + (size_t)l * DIM * INTER; dl = g_w2l + (size_t)l * DIM * INTER; }
    int cx = blockIdx.x * 32, ry = blockIdx.y * 32;
    if (cx >= C || ry >= R) return;
    __shared__ float tl[32][33];
    int tx = threadIdx.x, ty = threadIdx.y;
    #pragma unroll
    for (int i = 0; i < 4; i++)
        tl[ty * 4 + i][tx] = src[(size_t)(ry + ty * 4 + i) * C + cx + tx];
    __syncthreads();
    #pragma unroll
    for (int i = 0; i < 4; i++) {
        float w = tl[tx][ty * 4 + i];
        __nv_bfloat16 hi = __float2bfloat16_rn(w);
        size_t o = (size_t)(cx + ty * 4 + i) * R + ry + tx;
        dh[o] = hi;
        dl[o] = __float2bfloat16_rn(w - __bfloat162float(hi));
    }
}

// ---------------- upsample ----------------
__global__ void upsample_kernel(const int* __restrict__ seq_len, float* __restrict__ out) {
    int bp = blockIdx.x;
    int b = bp >> 12, p = bp & 4095;
    int al = seq_len[b];
    float4* orow = (float4*)(out + (size_t)bp * DIM);
    if (p >= al) {
        for (int c = threadIdx.x; c < DIM / 4; c += blockDim.x)
            orow[c] = make_float4(0.f, 0.f, 0.f, 0.f);
        return;
    }
    int base  = al >> 9;
    int rem   = al & 511;
    int split = (512 - rem) * base;
    int j = (p < split) ? (p / base) : ((512 - rem) + (p - split) / (base + 1));
    if (j > 511) j = 511;
    const float4* xrow = (const float4*)(g_x + (size_t)(b * SEQ + j) * DIM);
    for (int c = threadIdx.x; c < DIM / 4; c += blockDim.x) orow[c] = xrow[c];
}

// ---------------- launch ----------------
extern "C" void kernel_launch(void* const* d_in, const int* in_sizes, int n_in,
                              void* d_out, int out_size) {
    const int*   text    = (const int*)  d_in[0];
    const int*   seq_len = (const int*)  d_in[1];
    const float* emb     = (const float*)d_in[2];
    const float* dw_w    = (const float*)d_in[3];
    const float* dw_b    = (const float*)d_in[4];
    const float* ln_g    = (const float*)d_in[5];
    const float* ln_b    = (const float*)d_in[6];
    const float* pw1_w   = (const float*)d_in[7];
    const float* pw1_b   = (const float*)d_in[8];
    const float* grn_g   = (const float*)d_in[9];
    const float* grn_b   = (const float*)d_in[10];
    const float* pw2_w   = (const float*)d_in[11];
    const float* pw2_b   = (const float*)d_in[12];
    float* out = (float*)d_out;

    static const int SMEM_BYTES = NSTAGE * (int)STAGE_BYTES;  // 96 KB
    cudaFuncSetAttribute(gemm1_mma, cudaFuncAttributeMaxDynamicSharedMemorySize, SMEM_BYTES);
    cudaFuncSetAttribute(gemm2_mma, cudaFuncAttributeMaxDynamicSharedMemorySize, SMEM_BYTES);

    prep_w<<<dim3(32, 32, 2 * NLAYERS), dim3(32, 8)>>>(pw1_w, pw2_w);
    embed_kernel<<<NB * SEQ, 256>>>(text, emb);
    for (int l = 0; l < NLAYERS; l++) {
        convln_kernel<<<NB * P1, 128>>>(dw_w + l * 7 * DIM, dw_b + l * DIM,
                                        ln_g + l * DIM, ln_b + l * DIM);
        gemm1_mma<<<dim3(INTER / 128, M1T), 128, SMEM_BYTES>>>(l, pw1_b + l * INTER);
        alpha_kernel<<<NB, 1024>>>(grn_g + l * INTER);
        transform_kernel<<<NB * SEQ, 256>>>(grn_b + l * INTER);
        gemm2_mma<<<dim3(DIM / 128, NB * SEQ / 128, 2), 128, SMEM_BYTES>>>(l, pw2_b + l * DIM);
    }
    upsample_kernel<<<NB * MAXSEQ, 128>>>(seq_len, out);
}